// round 1
// baseline (speedup 1.0000x reference)
#include <cuda_runtime.h>
#include <cuda_bf16.h>
#include <math.h>

// Problem constants (fixed by the reference setup)
#define BS   2
#define T_   4
#define HS   32
#define WS   32
#define HW   (HS*WS)          // 1024
#define LQ   (T_*HW)          // 4096
#define M_TOK (BS*LQ)         // 8192 rows
#define D_   256
#define NH   8
#define NL   4
#define NP   4
#define HD   32               // D/NH
#define DFFN 1024
#define X_ELEMS   (BS*LQ*D_)              // 2097152 (output x)
#define SLOC_ELEMS (BS*LQ*NH*NL*NP*2)     // 2097152 (sampling_locations)

// ---------------- scratch (no allocations allowed) ----------------
__device__ float g_value[M_TOK * D_];       // (m, h*32+d)
__device__ float g_aw[M_TOK * NH * NL * NP];// logits then softmaxed weights (m, 128)
__device__ float g_attn[M_TOK * D_];        // attn out, later reused for pre-LN2
__device__ float g_x1[M_TOK * D_];          // after LN1
__device__ float g_ffn[M_TOK * DFFN];       // pre-LN1 temp (first 8MB), then FFN hidden

// ---------------- generic tiled SGEMM with fused epilogues ----------------
// C[M,N] = A[M,K] @ B[K,N]  (+epilogue)
// epi: 0 = +bias
//      1 = sampling-locations: out = (acc+bias)/32 + ref[row, l, c]   (N must be 256)
//      2 = relu(acc+bias)
//      3 = acc + bias + res[row*N+col]
#define BM 64
#define BN 64
#define BKK 16

__global__ __launch_bounds__(256)
void sgemm_kernel(const float* __restrict__ A, const float* __restrict__ B,
                  const float* __restrict__ bias, const float* __restrict__ res,
                  const float* __restrict__ ref, float* __restrict__ C,
                  int M, int N, int K, int epi)
{
    __shared__ float As[BKK][BM + 1];
    __shared__ float Bs[BKK][BN];

    const int tid = threadIdx.x;
    const int tx = tid & 15;        // 0..15 -> N direction
    const int ty = tid >> 4;        // 0..15 -> M direction
    const int row0 = blockIdx.y * BM;
    const int col0 = blockIdx.x * BN;

    const int arow = tid >> 2;          // 0..63
    const int acol = (tid & 3) * 4;     // 0,4,8,12
    const int brow = tid >> 4;          // 0..15
    const int bcol = (tid & 15) * 4;    // 0..60

    float acc[4][4];
#pragma unroll
    for (int i = 0; i < 4; i++)
#pragma unroll
        for (int j = 0; j < 4; j++) acc[i][j] = 0.f;

    for (int kt = 0; kt < K; kt += BKK) {
        float4 a4 = *(const float4*)(A + (size_t)(row0 + arow) * K + kt + acol);
        As[acol + 0][arow] = a4.x;
        As[acol + 1][arow] = a4.y;
        As[acol + 2][arow] = a4.z;
        As[acol + 3][arow] = a4.w;
        float4 b4 = *(const float4*)(B + (size_t)(kt + brow) * N + col0 + bcol);
        *(float4*)&Bs[brow][bcol] = b4;
        __syncthreads();

#pragma unroll
        for (int kk = 0; kk < BKK; kk++) {
            float af[4], bf[4];
#pragma unroll
            for (int i = 0; i < 4; i++) af[i] = As[kk][ty * 4 + i];
#pragma unroll
            for (int j = 0; j < 4; j++) bf[j] = Bs[kk][tx * 4 + j];
#pragma unroll
            for (int i = 0; i < 4; i++)
#pragma unroll
                for (int j = 0; j < 4; j++)
                    acc[i][j] = fmaf(af[i], bf[j], acc[i][j]);
        }
        __syncthreads();
    }

#pragma unroll
    for (int i = 0; i < 4; i++) {
        const int row = row0 + ty * 4 + i;
#pragma unroll
        for (int j = 0; j < 4; j++) {
            const int col = col0 + tx * 4 + j;
            float v = acc[i][j] + bias[col];
            if (epi == 1) {
                const int l = (col >> 3) & 3;
                const int c = col & 1;
                v = v * (1.f / 32.f) + ref[((size_t)row * NL + l) * 2 + c];
            } else if (epi == 2) {
                v = fmaxf(v, 0.f);
            } else if (epi == 3) {
                v += res[(size_t)row * N + col];
            }
            C[(size_t)row * N + col] = v;
        }
    }
}

// ---------------- softmax over 16 per (b,q,h) ----------------
__global__ void softmax16_kernel(float* __restrict__ aw)
{
    const int idx = blockIdx.x * blockDim.x + threadIdx.x; // 0 .. M_TOK*NH-1
    if (idx >= M_TOK * NH) return;
    float* p = aw + (size_t)idx * 16;
    float v[16];
    float mx = -1e30f;
#pragma unroll
    for (int i = 0; i < 16; i++) { v[i] = p[i]; mx = fmaxf(mx, v[i]); }
    float s = 0.f;
#pragma unroll
    for (int i = 0; i < 16; i++) { v[i] = __expf(v[i] - mx); s += v[i]; }
    const float inv = 1.f / s;
#pragma unroll
    for (int i = 0; i < 16; i++) p[i] = v[i] * inv;
}

// ---------------- deformable bilinear gather + weighted sum ----------------
// one block per token m; warp per head; lane = head-dim element
__global__ __launch_bounds__(256)
void gather_kernel(const float* __restrict__ value, const float* __restrict__ slocs,
                   const float* __restrict__ aw, float* __restrict__ attn)
{
    const int m = blockIdx.x;           // token index in [0, M_TOK)
    const int h = threadIdx.x >> 5;
    const int d = threadIdx.x & 31;
    const int b = m >> 12;              // /4096

    const float* sl = slocs + (((size_t)m * NH + h) * NL * NP) * 2;
    const float* w  = aw + (size_t)m * (NH * NL * NP) + h * (NL * NP);

    float acc = 0.f;
#pragma unroll
    for (int l = 0; l < NL; l++) {
        const size_t vbase = ((size_t)b * LQ + (size_t)l * HW);
#pragma unroll
        for (int p = 0; p < NP; p++) {
            const int s = l * NP + p;
            const float x = sl[2 * s]     * (float)WS - 0.5f;
            const float y = sl[2 * s + 1] * (float)HS - 0.5f;
            const float ww = w[s];
            const float x0f = floorf(x);
            const float y0f = floorf(y);
            const int x0 = (int)x0f;
            const int y0 = (int)y0f;
            const float lx = x - x0f;
            const float ly = y - y0f;
#pragma unroll
            for (int dy = 0; dy < 2; dy++) {
                const int yi = y0 + dy;
                if (yi < 0 || yi >= HS) continue;
                const float wy = dy ? ly : (1.f - ly);
#pragma unroll
                for (int dx = 0; dx < 2; dx++) {
                    const int xi = x0 + dx;
                    if (xi < 0 || xi >= WS) continue;
                    const float wx = dx ? lx : (1.f - lx);
                    const size_t vrow = vbase + (size_t)yi * WS + xi;
                    acc = fmaf(ww * wy * wx,
                               value[(vrow * NH + h) * HD + d], acc);
                }
            }
        }
    }
    attn[(size_t)m * D_ + h * HD + d] = acc;
}

// ---------------- layernorm over 256 cols; one warp per row ----------------
__global__ __launch_bounds__(256)
void layernorm_kernel(const float* __restrict__ in, const float* __restrict__ g,
                      const float* __restrict__ b, float* __restrict__ out)
{
    const int row = blockIdx.x * 8 + (threadIdx.x >> 5);
    const int lane = threadIdx.x & 31;
    const float* r = in + (size_t)row * D_;
    float v[8];
    float s = 0.f, s2 = 0.f;
#pragma unroll
    for (int i = 0; i < 8; i++) {
        v[i] = r[i * 32 + lane];
        s += v[i];
        s2 = fmaf(v[i], v[i], s2);
    }
#pragma unroll
    for (int o = 16; o > 0; o >>= 1) {
        s  += __shfl_xor_sync(0xffffffff, s, o);
        s2 += __shfl_xor_sync(0xffffffff, s2, o);
    }
    const float mean = s * (1.f / 256.f);
    const float var  = s2 * (1.f / 256.f) - mean * mean;
    const float inv  = rsqrtf(var + 1e-5f);
    float* o = out + (size_t)row * D_;
#pragma unroll
    for (int i = 0; i < 8; i++) {
        const int c = i * 32 + lane;
        o[c] = (v[i] - mean) * inv * g[c] + b[c];
    }
}

// ---------------- host launch ----------------
extern "C" void kernel_launch(void* const* d_in, const int* in_sizes, int n_in,
                              void* d_out, int out_size)
{
    const float* src    = (const float*)d_in[0];
    // d_in[1] = pos (unused by the reference forward)
    const float* refpts = (const float*)d_in[2];
    const float* vp_w   = (const float*)d_in[3];
    const float* vp_b   = (const float*)d_in[4];
    const float* so_w   = (const float*)d_in[5];
    const float* so_b   = (const float*)d_in[6];
    const float* aw_w   = (const float*)d_in[7];
    const float* aw_b   = (const float*)d_in[8];
    const float* op_w   = (const float*)d_in[9];
    const float* op_b   = (const float*)d_in[10];
    const float* n1_g   = (const float*)d_in[11];
    const float* n1_b   = (const float*)d_in[12];
    const float* l1_w   = (const float*)d_in[13];
    const float* l1_b   = (const float*)d_in[14];
    const float* l2_w   = (const float*)d_in[15];
    const float* l2_b   = (const float*)d_in[16];
    const float* n2_g   = (const float*)d_in[17];
    const float* n2_b   = (const float*)d_in[18];

    float* out_x  = (float*)d_out;
    float* slocs  = (float*)d_out + X_ELEMS;

    float* value = nullptr; cudaGetSymbolAddress((void**)&value, g_value);
    float* aw    = nullptr; cudaGetSymbolAddress((void**)&aw,    g_aw);
    float* attn  = nullptr; cudaGetSymbolAddress((void**)&attn,  g_attn);
    float* x1    = nullptr; cudaGetSymbolAddress((void**)&x1,    g_x1);
    float* ffn   = nullptr; cudaGetSymbolAddress((void**)&ffn,   g_ffn);

    const dim3 blk(256);
    const dim3 grid_d(D_ / BN,  M_TOK / BM);   // (4, 128)
    const dim3 grid_l(128 / BN, M_TOK / BM);   // (2, 128)
    const dim3 grid_f(DFFN / BN, M_TOK / BM);  // (16, 128)

    // 1) value = x @ Wv + bv
    sgemm_kernel<<<grid_d, blk>>>(src, vp_w, vp_b, nullptr, nullptr, value,
                                  M_TOK, D_, D_, 0);
    // 2) sampling_locations = ref + (x @ Wo + bo)/32  (direct to output)
    sgemm_kernel<<<grid_d, blk>>>(src, so_w, so_b, nullptr, refpts, slocs,
                                  M_TOK, D_, D_, 1);
    // 3) attention logits
    sgemm_kernel<<<grid_l, blk>>>(src, aw_w, aw_b, nullptr, nullptr, aw,
                                  M_TOK, 128, D_, 0);
    // 4) softmax over 16
    softmax16_kernel<<<(M_TOK * NH + 255) / 256, 256>>>(aw);
    // 5) deformable gather
    gather_kernel<<<M_TOK, 256>>>(value, slocs, aw, attn);
    // 6) out_proj + residual(src) -> pre-LN1 (reuse ffn buffer)
    sgemm_kernel<<<grid_d, blk>>>(attn, op_w, op_b, src, nullptr, ffn,
                                  M_TOK, D_, D_, 3);
    // 7) LN1 -> x1
    layernorm_kernel<<<M_TOK / 8, 256>>>(ffn, n1_g, n1_b, x1);
    // 8) FFN1: relu(x1 @ W1 + b1) -> ffn (full 8192x1024)
    sgemm_kernel<<<grid_f, blk>>>(x1, l1_w, l1_b, nullptr, nullptr, ffn,
                                  M_TOK, DFFN, D_, 2);
    // 9) FFN2 + residual(x1) -> pre-LN2 (reuse attn buffer)
    sgemm_kernel<<<grid_d, blk>>>(ffn, l2_w, l2_b, x1, nullptr, attn,
                                  M_TOK, D_, DFFN, 3);
    // 10) LN2 -> final x output
    layernorm_kernel<<<M_TOK / 8, 256>>>(attn, n2_g, n2_b, out_x);
}

// round 4
// speedup vs baseline: 1.1157x; 1.1157x over previous
#include <cuda_runtime.h>
#include <cuda_bf16.h>
#include <math.h>

// Problem constants (fixed by the reference setup)
#define BS   2
#define T_   4
#define HS   32
#define WS   32
#define HW   (HS*WS)          // 1024
#define LQ   (T_*HW)          // 4096
#define M_TOK (BS*LQ)         // 8192 rows
#define D_   256
#define NH   8
#define NL   4
#define NP   4
#define HD   32               // D/NH
#define DFFN 1024
#define X_ELEMS   (BS*LQ*D_)              // 2097152 (output x)

// ---------------- scratch (no allocations allowed) ----------------
__device__ float g_value[M_TOK * D_];       // (m, h*32+d)
__device__ float g_aw[M_TOK * NH * NL * NP];// logits then softmaxed weights (m, 128)
__device__ float g_attn[M_TOK * D_];        // attn out, later reused for pre-LN2
__device__ float g_x1[M_TOK * D_];          // after LN1
__device__ float g_ffn[M_TOK * DFFN];       // pre-LN1 temp (first 8MB), then FFN hidden

// ---------------- high-throughput tiled SGEMM with fused epilogues ----------
// C[M,N] = A[M,K] @ B[K,N]  (+epilogue)
// EPI: 0 = +bias
//      1 = sampling-locations: out = (acc+bias)/32 + ref[row, l, c]   (N==256)
//      2 = relu(acc+bias)
//      3 = acc + bias + res[row*N+col]
// Tile: BM=128 x BN_ (64 or 128), BK=8, 256 threads, TM=8 x TN_ per thread.

template<int BN_, int TN_, int EPI>
__global__ __launch_bounds__(256)
void sgemm(const float* __restrict__ A, const float* __restrict__ B,
           const float* __restrict__ bias, const float* __restrict__ res,
           const float* __restrict__ ref, float* __restrict__ C,
           int M, int N, int K)
{
    constexpr int BM = 128;
    constexpr int BK = 8;
    constexpr int TM = 8;

    __shared__ float As[BK][BM + 4];
    __shared__ float Bs[BK][BN_ + 4];

    const int tid = threadIdx.x;
    const int tx = tid & 15;          // 0..15 -> N direction
    const int ty = tid >> 4;          // 0..15 -> M direction
    const int row0 = blockIdx.y * BM;
    const int col0 = blockIdx.x * BN_;

    // A tile load: 128x8 floats = float4 per thread
    const int arow = tid >> 1;            // 0..127
    const int acol = (tid & 1) * 4;       // 0 or 4
    // B tile load: 8xBN_ floats
    const int bcol = (BN_ == 128) ? (tid & 31) * 4 : (tid & 31) * 2;
    const int brow = tid >> 5;            // 0..7

    const float* Aptr = A + (size_t)(row0 + arow) * K + acol;
    const float* Bptr = B + (size_t)brow * N + col0 + bcol;

    float acc[TM][TN_];
#pragma unroll
    for (int i = 0; i < TM; i++)
#pragma unroll
        for (int j = 0; j < TN_; j++) acc[i][j] = 0.f;

    const int ktiles = K / BK;

    // prologue: load tile 0
    {
        float4 a4 = *(const float4*)Aptr;
        As[acol + 0][arow] = a4.x;
        As[acol + 1][arow] = a4.y;
        As[acol + 2][arow] = a4.z;
        As[acol + 3][arow] = a4.w;
        if constexpr (BN_ == 128) {
            *(float4*)&Bs[brow][bcol] = *(const float4*)Bptr;
        } else {
            *(float2*)&Bs[brow][bcol] = *(const float2*)Bptr;
        }
    }
    __syncthreads();

    for (int kt = 1; kt <= ktiles; kt++) {
        float4 a4n;
        float4 b4n;
        b4n.x = 0.f; b4n.y = 0.f; b4n.z = 0.f; b4n.w = 0.f;
        const bool more = (kt < ktiles);
        if (more) {
            a4n = *(const float4*)(Aptr + (size_t)kt * BK);
            if constexpr (BN_ == 128) {
                b4n = *(const float4*)(Bptr + (size_t)kt * BK * N);
            } else {
                float2 t = *(const float2*)(Bptr + (size_t)kt * BK * N);
                b4n.x = t.x; b4n.y = t.y;
            }
        }

#pragma unroll
        for (int kk = 0; kk < BK; kk++) {
            float af[TM];
            *(float4*)&af[0] = *(const float4*)&As[kk][ty * TM];
            *(float4*)&af[4] = *(const float4*)&As[kk][ty * TM + 4];
            float bf[TN_];
            *(float4*)&bf[0] = *(const float4*)&Bs[kk][tx * TN_];
            if constexpr (TN_ == 8) {
                *(float4*)&bf[4] = *(const float4*)&Bs[kk][tx * TN_ + 4];
            }
#pragma unroll
            for (int i = 0; i < TM; i++)
#pragma unroll
                for (int j = 0; j < TN_; j++)
                    acc[i][j] = fmaf(af[i], bf[j], acc[i][j]);
        }

        if (more) {
            __syncthreads();
            As[acol + 0][arow] = a4n.x;
            As[acol + 1][arow] = a4n.y;
            As[acol + 2][arow] = a4n.z;
            As[acol + 3][arow] = a4n.w;
            if constexpr (BN_ == 128) {
                *(float4*)&Bs[brow][bcol] = b4n;
            } else {
                float2 t; t.x = b4n.x; t.y = b4n.y;
                *(float2*)&Bs[brow][bcol] = t;
            }
            __syncthreads();
        }
    }

    // epilogue
    float bcol_bias[TN_];
#pragma unroll
    for (int j = 0; j < TN_; j++) bcol_bias[j] = bias[col0 + tx * TN_ + j];

#pragma unroll
    for (int i = 0; i < TM; i++) {
        const int row = row0 + ty * TM + i;
        float* crow = C + (size_t)row * N + col0 + tx * TN_;
#pragma unroll
        for (int j0 = 0; j0 < TN_; j0 += 4) {
            float4 v;
            float* vp = &v.x;
            float4 r4;
            r4.x = 0.f; r4.y = 0.f; r4.z = 0.f; r4.w = 0.f;
            if constexpr (EPI == 3) {
                r4 = *(const float4*)(res + (size_t)row * N + col0 + tx * TN_ + j0);
            }
            const float* rp = &r4.x;
#pragma unroll
            for (int j = 0; j < 4; j++) {
                float u = acc[i][j0 + j] + bcol_bias[j0 + j];
                if constexpr (EPI == 1) {
                    const int col = col0 + tx * TN_ + j0 + j;
                    const int l = (col >> 3) & 3;
                    const int c = col & 1;
                    u = u * (1.f / 32.f) + ref[(size_t)row * 8 + l * 2 + c];
                } else if constexpr (EPI == 2) {
                    u = fmaxf(u, 0.f);
                } else if constexpr (EPI == 3) {
                    u += rp[j];
                }
                vp[j] = u;
            }
            *(float4*)(crow + j0) = v;
        }
    }
}

// ---------------- softmax over 16 per (b,q,h) ----------------
__global__ void softmax16_kernel(float* __restrict__ aw)
{
    const int idx = blockIdx.x * blockDim.x + threadIdx.x; // 0 .. M_TOK*NH-1
    if (idx >= M_TOK * NH) return;
    float4* p = (float4*)(aw + (size_t)idx * 16);
    float4 v4[4];
#pragma unroll
    for (int i = 0; i < 4; i++) v4[i] = p[i];
    float* v = &v4[0].x;
    float mx = -1e30f;
#pragma unroll
    for (int i = 0; i < 16; i++) mx = fmaxf(mx, v[i]);
    float s = 0.f;
#pragma unroll
    for (int i = 0; i < 16; i++) { v[i] = __expf(v[i] - mx); s += v[i]; }
    const float inv = 1.f / s;
#pragma unroll
    for (int i = 0; i < 16; i++) v[i] *= inv;
#pragma unroll
    for (int i = 0; i < 4; i++) p[i] = v4[i];
}

// ---------------- deformable bilinear gather + weighted sum ----------------
// one block per token m; warp per head; lane = head-dim element
__global__ __launch_bounds__(256)
void gather_kernel(const float* __restrict__ value, const float* __restrict__ slocs,
                   const float* __restrict__ aw, float* __restrict__ attn)
{
    const int m = blockIdx.x;           // token index in [0, M_TOK)
    const int h = threadIdx.x >> 5;
    const int d = threadIdx.x & 31;
    const int b = m >> 12;              // /4096

    const float* sl = slocs + (((size_t)m * NH + h) * NL * NP) * 2;
    const float* w  = aw + (size_t)m * (NH * NL * NP) + h * (NL * NP);

    float acc = 0.f;
#pragma unroll
    for (int l = 0; l < NL; l++) {
        const size_t vbase = ((size_t)b * LQ + (size_t)l * HW);
#pragma unroll
        for (int p = 0; p < NP; p++) {
            const int s = l * NP + p;
            const float x = sl[2 * s]     * (float)WS - 0.5f;
            const float y = sl[2 * s + 1] * (float)HS - 0.5f;
            const float ww = w[s];
            const float x0f = floorf(x);
            const float y0f = floorf(y);
            const int x0 = (int)x0f;
            const int y0 = (int)y0f;
            const float lx = x - x0f;
            const float ly = y - y0f;
#pragma unroll
            for (int dy = 0; dy < 2; dy++) {
                const int yi = y0 + dy;
                if (yi < 0 || yi >= HS) continue;
                const float wy = dy ? ly : (1.f - ly);
#pragma unroll
                for (int dx = 0; dx < 2; dx++) {
                    const int xi = x0 + dx;
                    if (xi < 0 || xi >= WS) continue;
                    const float wx = dx ? lx : (1.f - lx);
                    const size_t vrow = vbase + (size_t)yi * WS + xi;
                    acc = fmaf(ww * wy * wx,
                               value[(vrow * NH + h) * HD + d], acc);
                }
            }
        }
    }
    attn[(size_t)m * D_ + h * HD + d] = acc;
}

// ---------------- layernorm over 256 cols; one warp per row ----------------
__global__ __launch_bounds__(256)
void layernorm_kernel(const float* __restrict__ in, const float* __restrict__ g,
                      const float* __restrict__ b, float* __restrict__ out)
{
    const int row = blockIdx.x * 8 + (threadIdx.x >> 5);
    const int lane = threadIdx.x & 31;
    const float* r = in + (size_t)row * D_;
    float v[8];
    float s = 0.f, s2 = 0.f;
#pragma unroll
    for (int i = 0; i < 8; i++) {
        v[i] = r[i * 32 + lane];
        s += v[i];
        s2 = fmaf(v[i], v[i], s2);
    }
#pragma unroll
    for (int o = 16; o > 0; o >>= 1) {
        s  += __shfl_xor_sync(0xffffffff, s, o);
        s2 += __shfl_xor_sync(0xffffffff, s2, o);
    }
    const float mean = s * (1.f / 256.f);
    const float var  = s2 * (1.f / 256.f) - mean * mean;
    const float inv  = rsqrtf(var + 1e-5f);
    float* o = out + (size_t)row * D_;
#pragma unroll
    for (int i = 0; i < 8; i++) {
        const int c = i * 32 + lane;
        o[c] = (v[i] - mean) * inv * g[c] + b[c];
    }
}

// ---------------- host launch ----------------
extern "C" void kernel_launch(void* const* d_in, const int* in_sizes, int n_in,
                              void* d_out, int out_size)
{
    const float* src    = (const float*)d_in[0];
    // d_in[1] = pos (unused by the reference forward)
    const float* refpts = (const float*)d_in[2];
    const float* vp_w   = (const float*)d_in[3];
    const float* vp_b   = (const float*)d_in[4];
    const float* so_w   = (const float*)d_in[5];
    const float* so_b   = (const float*)d_in[6];
    const float* aw_w   = (const float*)d_in[7];
    const float* aw_b   = (const float*)d_in[8];
    const float* op_w   = (const float*)d_in[9];
    const float* op_b   = (const float*)d_in[10];
    const float* n1_g   = (const float*)d_in[11];
    const float* n1_b   = (const float*)d_in[12];
    const float* l1_w   = (const float*)d_in[13];
    const float* l1_b   = (const float*)d_in[14];
    const float* l2_w   = (const float*)d_in[15];
    const float* l2_b   = (const float*)d_in[16];
    const float* n2_g   = (const float*)d_in[17];
    const float* n2_b   = (const float*)d_in[18];

    float* out_x  = (float*)d_out;
    float* slocs  = (float*)d_out + X_ELEMS;

    float* value = nullptr; cudaGetSymbolAddress((void**)&value, g_value);
    float* aw    = nullptr; cudaGetSymbolAddress((void**)&aw,    g_aw);
    float* attn  = nullptr; cudaGetSymbolAddress((void**)&attn,  g_attn);
    float* x1    = nullptr; cudaGetSymbolAddress((void**)&x1,    g_x1);
    float* ffn   = nullptr; cudaGetSymbolAddress((void**)&ffn,   g_ffn);

    const dim3 blk(256);
    const dim3 grid_d64(D_ / 64, M_TOK / 128);    // (4, 64) = 256 blocks
    const dim3 grid_l64(128 / 64, M_TOK / 128);   // (2, 64) = 128 blocks
    const dim3 grid_f128(DFFN / 128, M_TOK / 128);// (8, 64) = 512 blocks

    // 1) value = x @ Wv + bv
    sgemm<64, 4, 0><<<grid_d64, blk>>>(src, vp_w, vp_b, nullptr, nullptr, value,
                                       M_TOK, D_, D_);
    // 2) sampling_locations = ref + (x @ Wo + bo)/32  (direct to output)
    sgemm<64, 4, 1><<<grid_d64, blk>>>(src, so_w, so_b, nullptr, refpts, slocs,
                                       M_TOK, D_, D_);
    // 3) attention logits
    sgemm<64, 4, 0><<<grid_l64, blk>>>(src, aw_w, aw_b, nullptr, nullptr, aw,
                                       M_TOK, 128, D_);
    // 4) softmax over 16
    softmax16_kernel<<<(M_TOK * NH + 255) / 256, 256>>>(aw);
    // 5) deformable gather
    gather_kernel<<<M_TOK, 256>>>(value, slocs, aw, attn);
    // 6) out_proj + residual(src) -> pre-LN1 (reuse ffn buffer)
    sgemm<64, 4, 3><<<grid_d64, blk>>>(attn, op_w, op_b, src, nullptr, ffn,
                                       M_TOK, D_, D_);
    // 7) LN1 -> x1
    layernorm_kernel<<<M_TOK / 8, 256>>>(ffn, n1_g, n1_b, x1);
    // 8) FFN1: relu(x1 @ W1 + b1) -> ffn (full 8192x1024)
    sgemm<128, 8, 2><<<grid_f128, blk>>>(x1, l1_w, l1_b, nullptr, nullptr, ffn,
                                         M_TOK, DFFN, D_);
    // 9) FFN2 + residual(x1) -> pre-LN2 (reuse attn buffer)
    sgemm<64, 4, 3><<<grid_d64, blk>>>(ffn, l2_w, l2_b, x1, nullptr, attn,
                                       M_TOK, D_, DFFN);
    // 10) LN2 -> final x output
    layernorm_kernel<<<M_TOK / 8, 256>>>(attn, n2_g, n2_b, out_x);
}

// round 6
// speedup vs baseline: 1.7586x; 1.5762x over previous
#include <cuda_runtime.h>
#include <cuda_bf16.h>
#include <math.h>
#include <stdint.h>

// Problem constants (fixed by the reference setup)
#define BS   2
#define T_   4
#define HS   32
#define WS   32
#define HW   (HS*WS)          // 1024
#define LQ   (T_*HW)          // 4096
#define M_TOK (BS*LQ)         // 8192 rows
#define D_   256
#define NH   8
#define NL   4
#define NP   4
#define HD   32               // D/NH
#define DFFN 1024
#define X_ELEMS   (BS*LQ*D_)              // 2097152 (output x)

// ---------------- scratch (no allocations allowed) ----------------
__device__ __nv_bfloat16 g_src_h[M_TOK * D_];
__device__ __nv_bfloat16 g_src_l[M_TOK * D_];
// transposed weights [N][K], hi/lo
#define WOFF_VP 0
#define WOFF_SO 65536
#define WOFF_AW 131072
#define WOFF_OP 163840
#define WOFF_L1 229376
#define WOFF_L2 491520
#define W_TOTAL 753664
__device__ __nv_bfloat16 g_w_h[W_TOTAL];
__device__ __nv_bfloat16 g_w_l[W_TOTAL];

__device__ float g_value[M_TOK * D_];        // value fp32 for gather
__device__ float g_aw[M_TOK * 128];          // logits -> softmax weights
__device__ __nv_bfloat16 g_attn_h[M_TOK * D_];
__device__ __nv_bfloat16 g_attn_l[M_TOK * D_];
__device__ float g_tmpf[M_TOK * D_];         // pre-LN buffer (reused)
__device__ float g_x1[M_TOK * D_];           // after LN1
__device__ __nv_bfloat16 g_x1_h[M_TOK * D_];
__device__ __nv_bfloat16 g_x1_l[M_TOK * D_];
__device__ __nv_bfloat16 g_ffn_h[M_TOK * DFFN];
__device__ __nv_bfloat16 g_ffn_l[M_TOK * DFFN];

// ---------------- warp MMA helpers (baseline PTX, no 'a' features) --------
__device__ __forceinline__ uint32_t smem_u32(const void* p) {
    uint32_t a;
    asm("{ .reg .u64 t; cvta.to.shared.u64 t, %1; cvt.u32.u64 %0, t; }" : "=r"(a) : "l"(p));
    return a;
}
__device__ __forceinline__ void ldm_x4(uint32_t* r, uint32_t addr) {
    asm volatile("ldmatrix.sync.aligned.m8n8.x4.shared.b16 {%0,%1,%2,%3}, [%4];"
                 : "=r"(r[0]), "=r"(r[1]), "=r"(r[2]), "=r"(r[3]) : "r"(addr));
}
__device__ __forceinline__ void mma_bf16(float* c, const uint32_t* a, const uint32_t* b) {
    asm volatile("mma.sync.aligned.m16n8k16.row.col.f32.bf16.bf16.f32 "
                 "{%0,%1,%2,%3}, {%4,%5,%6,%7}, {%8,%9}, {%0,%1,%2,%3};"
                 : "+f"(c[0]), "+f"(c[1]), "+f"(c[2]), "+f"(c[3])
                 : "r"(a[0]), "r"(a[1]), "r"(a[2]), "r"(a[3]), "r"(b[0]), "r"(b[1]));
}

// ---------------- bf16x3 tensor GEMM via mma.sync ----------------
// C[M,N] = A[M,K] @ W[K,N]; A hi/lo [M][K], Wt hi/lo [N][K]
// acc = Ah*Bh + Ah*Bl + Al*Bh  (fp32 accumulate)
// EPI: 0 = acc+bias (fp32)   1 = sloc   2 = relu -> hi/lo bf16   3 = +bias+res
#define AST 40   // smem row stride in bf16 elems (80B -> conflict-free ldmatrix)

template<int EPI>
__global__ __launch_bounds__(256)
void mma_gemm(const __nv_bfloat16* __restrict__ Ahi, const __nv_bfloat16* __restrict__ Alo,
              const __nv_bfloat16* __restrict__ Bhi, const __nv_bfloat16* __restrict__ Blo,
              const float* __restrict__ bias, const float* __restrict__ res,
              const float* __restrict__ ref, float* __restrict__ C,
              __nv_bfloat16* __restrict__ Chi, __nv_bfloat16* __restrict__ Clo,
              int N, int K)
{
    __shared__ __nv_bfloat16 sAh[128 * AST];
    __shared__ __nv_bfloat16 sAl[128 * AST];
    __shared__ __nv_bfloat16 sBh[64 * AST];
    __shared__ __nv_bfloat16 sBl[64 * AST];

    const int tid  = threadIdx.x;
    const int wid  = tid >> 5;
    const int lane = tid & 31;
    const int wm   = wid >> 1;          // 0..3  (M dir, 32 rows each)
    const int wn   = wid & 1;           // 0..1  (N dir, 32 cols each)
    const int m0   = blockIdx.y * 128;
    const int n0   = blockIdx.x * 64;

    const int seg = lane >> 3;
    const int rr  = lane & 7;

    // ldmatrix lane addresses (byte offsets into smem arrays)
    const uint32_t ah_base = smem_u32(sAh);
    const uint32_t al_base = smem_u32(sAl);
    const uint32_t bh_base = smem_u32(sBh);
    const uint32_t bl_base = smem_u32(sBl);

    uint32_t aoff[2], boff[2];
#pragma unroll
    for (int i = 0; i < 2; i++) {
        const int row = wm * 32 + i * 16 + (seg & 1) * 8 + rr;
        aoff[i] = (uint32_t)((row * AST + (seg >> 1) * 8) * 2);
    }
#pragma unroll
    for (int j = 0; j < 2; j++) {
        const int nrow = wn * 32 + j * 16 + ((seg >> 1) ? 8 : 0) + rr;
        boff[j] = (uint32_t)((nrow * AST + (seg & 1) * 8) * 2);
    }

    float acc[2][4][4];
#pragma unroll
    for (int i = 0; i < 2; i++)
#pragma unroll
        for (int j = 0; j < 4; j++)
#pragma unroll
            for (int q = 0; q < 4; q++) acc[i][j][q] = 0.f;

    const int nchunks = K >> 5;   // K/32

    for (int kt = 0; kt < nchunks; kt++) {
        const int kc = kt << 5;
        // global -> smem: A 128x32 (2 uint4/thread), B 64x32 (1 uint4/thread), hi+lo
#pragma unroll
        for (int it = 0; it < 2; it++) {
            const int idx = it * 256 + tid;     // 0..511
            const int row = idx >> 2;
            const int c8 = (idx & 3) * 8;
            const size_t gi = (size_t)(m0 + row) * K + kc + c8;
            *(uint4*)&sAh[row * AST + c8] = *(const uint4*)(Ahi + gi);
            *(uint4*)&sAl[row * AST + c8] = *(const uint4*)(Alo + gi);
        }
        {
            const int row = tid >> 2;
            const int c8 = (tid & 3) * 8;
            const size_t gi = (size_t)(n0 + row) * K + kc + c8;
            *(uint4*)&sBh[row * AST + c8] = *(const uint4*)(Bhi + gi);
            *(uint4*)&sBl[row * AST + c8] = *(const uint4*)(Blo + gi);
        }
        __syncthreads();

#pragma unroll
        for (int kk = 0; kk < 2; kk++) {
            const uint32_t kb = kk * 32;   // 16 bf16 = 32 bytes
            uint32_t ah[2][4], al[2][4], bh[2][4], bl[2][4];
#pragma unroll
            for (int i = 0; i < 2; i++) {
                ldm_x4(ah[i], ah_base + aoff[i] + kb);
                ldm_x4(al[i], al_base + aoff[i] + kb);
            }
#pragma unroll
            for (int j = 0; j < 2; j++) {
                ldm_x4(bh[j], bh_base + boff[j] + kb);
                ldm_x4(bl[j], bl_base + boff[j] + kb);
            }
#pragma unroll
            for (int i = 0; i < 2; i++) {
#pragma unroll
                for (int jt = 0; jt < 4; jt++) {
                    const int j = jt >> 1;
                    const int po = (jt & 1) * 2;
                    uint32_t bhp[2] = { bh[j][po], bh[j][po + 1] };
                    uint32_t blp[2] = { bl[j][po], bl[j][po + 1] };
                    mma_bf16(acc[i][jt], ah[i], bhp);
                    mma_bf16(acc[i][jt], ah[i], blp);
                    mma_bf16(acc[i][jt], al[i], bhp);
                }
            }
        }
        __syncthreads();
    }

    // -------- epilogue --------
    const int tg = lane >> 2;        // row-in-8
    const int t4 = lane & 3;         // col group

#pragma unroll
    for (int i = 0; i < 2; i++) {
#pragma unroll
        for (int jt = 0; jt < 4; jt++) {
            const int colg = n0 + wn * 32 + jt * 8 + t4 * 2;  // even col, 2 wide
            const float b0 = bias[colg];
            const float b1 = bias[colg + 1];
#pragma unroll
            for (int half = 0; half < 2; half++) {
                const int row = m0 + wm * 32 + i * 16 + tg + half * 8;
                float v0 = acc[i][jt][half * 2 + 0] + b0;
                float v1 = acc[i][jt][half * 2 + 1] + b1;
                if (EPI == 1) {
                    // col -> (l = (col>>3)&3, c = col&1); colg even -> c: 0,1
                    const int l = (colg >> 3) & 3;
                    const float r0 = ref[(size_t)row * 8 + l * 2 + 0];
                    const float r1 = ref[(size_t)row * 8 + l * 2 + 1];
                    v0 = v0 * (1.f / 32.f) + r0;
                    v1 = v1 * (1.f / 32.f) + r1;
                } else if (EPI == 3) {
                    const float2 rv = *(const float2*)(res + (size_t)row * N + colg);
                    v0 += rv.x; v1 += rv.y;
                }
                if (EPI == 2) {
                    v0 = fmaxf(v0, 0.f);
                    v1 = fmaxf(v1, 0.f);
                    const __nv_bfloat16 h0 = __float2bfloat16(v0);
                    const __nv_bfloat16 h1 = __float2bfloat16(v1);
                    __nv_bfloat162 hp, lp;
                    hp.x = h0; hp.y = h1;
                    lp.x = __float2bfloat16(v0 - __bfloat162float(h0));
                    lp.y = __float2bfloat16(v1 - __bfloat162float(h1));
                    *(__nv_bfloat162*)(Chi + (size_t)row * N + colg) = hp;
                    *(__nv_bfloat162*)(Clo + (size_t)row * N + colg) = lp;
                } else {
                    float2 o; o.x = v0; o.y = v1;
                    *(float2*)(C + (size_t)row * N + colg) = o;
                }
            }
        }
    }
}

// ---------------- fp32 -> hi/lo bf16 elementwise ----------------
__global__ void conv_hl_kernel(const float* __restrict__ x,
                               __nv_bfloat16* __restrict__ h, __nv_bfloat16* __restrict__ l,
                               int n)
{
    const int i = blockIdx.x * blockDim.x + threadIdx.x;
    if (i >= n) return;
    const float v = x[i];
    const __nv_bfloat16 hv = __float2bfloat16(v);
    h[i] = hv;
    l[i] = __float2bfloat16(v - __bfloat162float(hv));
}

// ---------------- weight transpose + split: W[K,N] -> Wt(hi/lo)[N,K] --------
__global__ void prep_w_kernel(const float* __restrict__ W,
                              __nv_bfloat16* __restrict__ h, __nv_bfloat16* __restrict__ l,
                              int K, int N)
{
    const int i = blockIdx.x * blockDim.x + threadIdx.x;
    if (i >= K * N) return;
    const int n = i / K;
    const int k = i - n * K;
    const float v = W[(size_t)k * N + n];
    const __nv_bfloat16 hv = __float2bfloat16(v);
    h[i] = hv;
    l[i] = __float2bfloat16(v - __bfloat162float(hv));
}

// ---------------- softmax over 16 per (b,q,h) ----------------
__global__ void softmax16_kernel(float* __restrict__ aw)
{
    const int idx = blockIdx.x * blockDim.x + threadIdx.x;
    if (idx >= M_TOK * NH) return;
    float4* p = (float4*)(aw + (size_t)idx * 16);
    float4 v4[4];
#pragma unroll
    for (int i = 0; i < 4; i++) v4[i] = p[i];
    float* v = &v4[0].x;
    float mx = -1e30f;
#pragma unroll
    for (int i = 0; i < 16; i++) mx = fmaxf(mx, v[i]);
    float s = 0.f;
#pragma unroll
    for (int i = 0; i < 16; i++) { v[i] = __expf(v[i] - mx); s += v[i]; }
    const float inv = 1.f / s;
#pragma unroll
    for (int i = 0; i < 16; i++) v[i] *= inv;
#pragma unroll
    for (int i = 0; i < 4; i++) p[i] = v4[i];
}

// ---------------- deformable bilinear gather; emits hi/lo bf16 -------------
__global__ __launch_bounds__(256)
void gather_kernel(const float* __restrict__ value, const float* __restrict__ slocs,
                   const float* __restrict__ aw,
                   __nv_bfloat16* __restrict__ outh, __nv_bfloat16* __restrict__ outl)
{
    const int m = blockIdx.x;
    const int h = threadIdx.x >> 5;
    const int d = threadIdx.x & 31;
    const int b = m >> 12;

    const float* sl = slocs + (((size_t)m * NH + h) * NL * NP) * 2;
    const float* w  = aw + (size_t)m * (NH * NL * NP) + h * (NL * NP);

    float acc = 0.f;
#pragma unroll
    for (int l = 0; l < NL; l++) {
        const size_t vbase = ((size_t)b * LQ + (size_t)l * HW);
#pragma unroll
        for (int p = 0; p < NP; p++) {
            const int s = l * NP + p;
            const float x = sl[2 * s]     * (float)WS - 0.5f;
            const float y = sl[2 * s + 1] * (float)HS - 0.5f;
            const float ww = w[s];
            const float x0f = floorf(x);
            const float y0f = floorf(y);
            const int x0 = (int)x0f;
            const int y0 = (int)y0f;
            const float lx = x - x0f;
            const float ly = y - y0f;
#pragma unroll
            for (int dy = 0; dy < 2; dy++) {
                const int yi = y0 + dy;
                if (yi < 0 || yi >= HS) continue;
                const float wy = dy ? ly : (1.f - ly);
#pragma unroll
                for (int dx = 0; dx < 2; dx++) {
                    const int xi = x0 + dx;
                    if (xi < 0 || xi >= WS) continue;
                    const float wx = dx ? lx : (1.f - lx);
                    const size_t vrow = vbase + (size_t)yi * WS + xi;
                    acc = fmaf(ww * wy * wx, value[(vrow * NH + h) * HD + d], acc);
                }
            }
        }
    }
    const size_t oi = (size_t)m * D_ + h * HD + d;
    const __nv_bfloat16 hv = __float2bfloat16(acc);
    outh[oi] = hv;
    outl[oi] = __float2bfloat16(acc - __bfloat162float(hv));
}

// ---------------- layernorm over 256 cols; one warp per row ----------------
template<int MODE>
__global__ __launch_bounds__(256)
void layernorm_kernel(const float* __restrict__ in, const float* __restrict__ g,
                      const float* __restrict__ b, float* __restrict__ out,
                      __nv_bfloat16* __restrict__ outh, __nv_bfloat16* __restrict__ outl)
{
    const int row = blockIdx.x * 8 + (threadIdx.x >> 5);
    const int lane = threadIdx.x & 31;
    const float* r = in + (size_t)row * D_;
    float v[8];
    float s = 0.f, s2 = 0.f;
#pragma unroll
    for (int i = 0; i < 8; i++) {
        v[i] = r[i * 32 + lane];
        s += v[i];
        s2 = fmaf(v[i], v[i], s2);
    }
#pragma unroll
    for (int o = 16; o > 0; o >>= 1) {
        s  += __shfl_xor_sync(0xffffffff, s, o);
        s2 += __shfl_xor_sync(0xffffffff, s2, o);
    }
    const float mean = s * (1.f / 256.f);
    const float var  = s2 * (1.f / 256.f) - mean * mean;
    const float inv  = rsqrtf(var + 1e-5f);
#pragma unroll
    for (int i = 0; i < 8; i++) {
        const int c = i * 32 + lane;
        const float u = (v[i] - mean) * inv * g[c] + b[c];
        out[(size_t)row * D_ + c] = u;
        if (MODE == 1) {
            const __nv_bfloat16 hv = __float2bfloat16(u);
            outh[(size_t)row * D_ + c] = hv;
            outl[(size_t)row * D_ + c] = __float2bfloat16(u - __bfloat162float(hv));
        }
    }
}

// ---------------- host launch ----------------
extern "C" void kernel_launch(void* const* d_in, const int* in_sizes, int n_in,
                              void* d_out, int out_size)
{
    const float* src    = (const float*)d_in[0];
    // d_in[1] = pos (unused by the reference forward)
    const float* refpts = (const float*)d_in[2];
    const float* vp_w   = (const float*)d_in[3];
    const float* vp_b   = (const float*)d_in[4];
    const float* so_w   = (const float*)d_in[5];
    const float* so_b   = (const float*)d_in[6];
    const float* aw_w   = (const float*)d_in[7];
    const float* aw_b   = (const float*)d_in[8];
    const float* op_w   = (const float*)d_in[9];
    const float* op_b   = (const float*)d_in[10];
    const float* n1_g   = (const float*)d_in[11];
    const float* n1_b   = (const float*)d_in[12];
    const float* l1_w   = (const float*)d_in[13];
    const float* l1_b   = (const float*)d_in[14];
    const float* l2_w   = (const float*)d_in[15];
    const float* l2_b   = (const float*)d_in[16];
    const float* n2_g   = (const float*)d_in[17];
    const float* n2_b   = (const float*)d_in[18];

    float* out_x = (float*)d_out;
    float* slocs = (float*)d_out + X_ELEMS;

    __nv_bfloat16 *src_h, *src_l, *w_h, *w_l, *attn_h, *attn_l, *x1_h, *x1_l, *ffn_h, *ffn_l;
    float *value, *aw, *tmpf, *x1;
    cudaGetSymbolAddress((void**)&src_h, g_src_h);
    cudaGetSymbolAddress((void**)&src_l, g_src_l);
    cudaGetSymbolAddress((void**)&w_h,   g_w_h);
    cudaGetSymbolAddress((void**)&w_l,   g_w_l);
    cudaGetSymbolAddress((void**)&value, g_value);
    cudaGetSymbolAddress((void**)&aw,    g_aw);
    cudaGetSymbolAddress((void**)&attn_h, g_attn_h);
    cudaGetSymbolAddress((void**)&attn_l, g_attn_l);
    cudaGetSymbolAddress((void**)&tmpf,  g_tmpf);
    cudaGetSymbolAddress((void**)&x1,    g_x1);
    cudaGetSymbolAddress((void**)&x1_h,  g_x1_h);
    cudaGetSymbolAddress((void**)&x1_l,  g_x1_l);
    cudaGetSymbolAddress((void**)&ffn_h, g_ffn_h);
    cudaGetSymbolAddress((void**)&ffn_l, g_ffn_l);

    // 0) conversions
    conv_hl_kernel<<<(M_TOK * D_ + 255) / 256, 256>>>(src, src_h, src_l, M_TOK * D_);
    prep_w_kernel<<<(256 * 256 + 255) / 256, 256>>>(vp_w, w_h + WOFF_VP, w_l + WOFF_VP, 256, 256);
    prep_w_kernel<<<(256 * 256 + 255) / 256, 256>>>(so_w, w_h + WOFF_SO, w_l + WOFF_SO, 256, 256);
    prep_w_kernel<<<(256 * 128 + 255) / 256, 256>>>(aw_w, w_h + WOFF_AW, w_l + WOFF_AW, 256, 128);
    prep_w_kernel<<<(256 * 256 + 255) / 256, 256>>>(op_w, w_h + WOFF_OP, w_l + WOFF_OP, 256, 256);
    prep_w_kernel<<<(256 * 1024 + 255) / 256, 256>>>(l1_w, w_h + WOFF_L1, w_l + WOFF_L1, 256, 1024);
    prep_w_kernel<<<(1024 * 256 + 255) / 256, 256>>>(l2_w, w_h + WOFF_L2, w_l + WOFF_L2, 1024, 256);

    const dim3 blk(256);
    const dim3 g256(256 / 64, M_TOK / 128);   // (4, 64)
    const dim3 g128(128 / 64, M_TOK / 128);   // (2, 64)
    const dim3 g1024(1024 / 64, M_TOK / 128); // (16, 64)

    // 1) value = src @ Wv + bv (fp32 for gather)
    mma_gemm<0><<<g256, blk>>>(src_h, src_l, w_h + WOFF_VP, w_l + WOFF_VP,
                               vp_b, nullptr, nullptr, value, nullptr, nullptr, 256, 256);
    // 2) sampling_locations -> output
    mma_gemm<1><<<g256, blk>>>(src_h, src_l, w_h + WOFF_SO, w_l + WOFF_SO,
                               so_b, nullptr, refpts, slocs, nullptr, nullptr, 256, 256);
    // 3) attention logits
    mma_gemm<0><<<g128, blk>>>(src_h, src_l, w_h + WOFF_AW, w_l + WOFF_AW,
                               aw_b, nullptr, nullptr, aw, nullptr, nullptr, 128, 256);
    // 4) softmax
    softmax16_kernel<<<(M_TOK * NH + 255) / 256, 256>>>(aw);
    // 5) gather -> attn hi/lo
    gather_kernel<<<M_TOK, 256>>>(value, slocs, aw, attn_h, attn_l);
    // 6) out_proj + residual(src) -> tmpf
    mma_gemm<3><<<g256, blk>>>(attn_h, attn_l, w_h + WOFF_OP, w_l + WOFF_OP,
                               op_b, src, nullptr, tmpf, nullptr, nullptr, 256, 256);
    // 7) LN1 -> x1 (fp32 + hi/lo)
    layernorm_kernel<1><<<M_TOK / 8, 256>>>(tmpf, n1_g, n1_b, x1, x1_h, x1_l);
    // 8) FFN1: relu -> ffn hi/lo
    mma_gemm<2><<<g1024, blk>>>(x1_h, x1_l, w_h + WOFF_L1, w_l + WOFF_L1,
                                l1_b, nullptr, nullptr, nullptr, ffn_h, ffn_l, 1024, 256);
    // 9) FFN2 + residual(x1) -> tmpf
    mma_gemm<3><<<g256, blk>>>(ffn_h, ffn_l, w_h + WOFF_L2, w_l + WOFF_L2,
                               l2_b, x1, nullptr, tmpf, nullptr, nullptr, 256, 1024);
    // 10) LN2 -> final output
    layernorm_kernel<0><<<M_TOK / 8, 256>>>(tmpf, n2_g, n2_b, out_x, nullptr, nullptr);
}

// round 8
// speedup vs baseline: 1.9406x; 1.1035x over previous
#include <cuda_runtime.h>
#include <cuda_bf16.h>
#include <math.h>
#include <stdint.h>

// Problem constants (fixed by the reference setup)
#define BS   2
#define T_   4
#define HS   32
#define WS   32
#define HW   (HS*WS)          // 1024
#define LQ   (T_*HW)          // 4096
#define M_TOK (BS*LQ)         // 8192 rows
#define D_   256
#define NH   8
#define NL   4
#define NP   4
#define HD   32               // D/NH
#define DFFN 1024
#define X_ELEMS   (BS*LQ*D_)              // 2097152 (output x)

// ---------------- scratch (no allocations allowed) ----------------
__device__ __nv_bfloat16 g_src_h[M_TOK * D_];
__device__ __nv_bfloat16 g_src_l[M_TOK * D_];
// transposed weights [N][K], hi/lo; fused layout: vp | so | aw | op | l1 | l2
#define WOFF_VP 0
#define WOFF_SO 65536
#define WOFF_AW 131072
#define WOFF_OP 163840
#define WOFF_L1 229376
#define WOFF_L2 491520
#define W_TOTAL 753664
__device__ __nv_bfloat16 g_w_h[W_TOTAL];
__device__ __nv_bfloat16 g_w_l[W_TOTAL];

__device__ float g_value[M_TOK * D_];        // value fp32 for gather
__device__ float g_aw[M_TOK * 128];          // attention LOGITS (softmax fused in gather)
__device__ __nv_bfloat16 g_attn_h[M_TOK * D_];
__device__ __nv_bfloat16 g_attn_l[M_TOK * D_];
__device__ float g_tmpf[M_TOK * D_];         // pre-LN buffer (reused)
__device__ float g_x1[M_TOK * D_];           // after LN1
__device__ __nv_bfloat16 g_x1_h[M_TOK * D_];
__device__ __nv_bfloat16 g_x1_l[M_TOK * D_];
__device__ __nv_bfloat16 g_ffn_h[M_TOK * DFFN];
__device__ __nv_bfloat16 g_ffn_l[M_TOK * DFFN];

// ---------------- warp MMA helpers (baseline PTX, no 'a' features) --------
__device__ __forceinline__ uint32_t smem_u32(const void* p) {
    uint32_t a;
    asm("{ .reg .u64 t; cvta.to.shared.u64 t, %1; cvt.u32.u64 %0, t; }" : "=r"(a) : "l"(p));
    return a;
}
__device__ __forceinline__ void ldm_x4(uint32_t* r, uint32_t addr) {
    asm volatile("ldmatrix.sync.aligned.m8n8.x4.shared.b16 {%0,%1,%2,%3}, [%4];"
                 : "=r"(r[0]), "=r"(r[1]), "=r"(r[2]), "=r"(r[3]) : "r"(addr));
}
__device__ __forceinline__ void mma_bf16(float* c, const uint32_t* a, const uint32_t* b) {
    asm volatile("mma.sync.aligned.m16n8k16.row.col.f32.bf16.bf16.f32 "
                 "{%0,%1,%2,%3}, {%4,%5,%6,%7}, {%8,%9}, {%0,%1,%2,%3};"
                 : "+f"(c[0]), "+f"(c[1]), "+f"(c[2]), "+f"(c[3])
                 : "r"(a[0]), "r"(a[1]), "r"(a[2]), "r"(a[3]), "r"(b[0]), "r"(b[1]));
}
#define CP16(dst, src) \
    asm volatile("cp.async.cg.shared.global [%0], [%1], 16;" :: "r"(dst), "l"(src))
#define CP_COMMIT() asm volatile("cp.async.commit_group;" ::: "memory")
#define CP_WAIT1()  asm volatile("cp.async.wait_group 1;"  ::: "memory")

// ---------------- bf16x3 tensor GEMM via mma.sync + cp.async pipeline ------
// C[M,N] = A[M,K] @ W[K,N]; A hi/lo [M][K], Wt hi/lo [N][K]
// acc = Ah*Bh + Ah*Bl + Al*Bh  (fp32 accumulate)
// EPI: 2 = relu -> hi/lo bf16   3 = +bias+res (fp32)
//      4 = fused src-projections: region by n0: [0,256)=value fp32,
//          [256,512)=sampling-loc, [512,640)=attn logits
#define AST 40                    // smem row stride (bf16): 80B rows, 16B aligned
#define SSTR 30720                // bytes per pipeline stage
#define OFF_AL 10240
#define OFF_BH 20480
#define OFF_BL 25600
#define SMEM_TOT (2 * SSTR)       // 61440 B dynamic smem

template<int EPI>
__global__ __launch_bounds__(256)
void mma_gemm(const __nv_bfloat16* __restrict__ Ahi, const __nv_bfloat16* __restrict__ Alo,
              const __nv_bfloat16* __restrict__ Bhi, const __nv_bfloat16* __restrict__ Blo,
              const float* __restrict__ bias, const float* __restrict__ bias2,
              const float* __restrict__ bias3,
              const float* __restrict__ res, const float* __restrict__ ref,
              float* __restrict__ C, float* __restrict__ C2, float* __restrict__ C3,
              __nv_bfloat16* __restrict__ Chi, __nv_bfloat16* __restrict__ Clo,
              int N, int K)
{
    extern __shared__ char smem[];
    const uint32_t sb = smem_u32(smem);

    const int tid  = threadIdx.x;
    const int wid  = tid >> 5;
    const int lane = tid & 31;
    const int wm   = wid >> 1;          // 0..3  (M dir, 32 rows each)
    const int wn   = wid & 1;           // 0..1  (N dir, 32 cols each)
    const int m0   = blockIdx.y * 128;
    const int n0   = blockIdx.x * 64;

    const int seg = lane >> 3;
    const int rr  = lane & 7;

    uint32_t aoff[2], boff[2];
#pragma unroll
    for (int i = 0; i < 2; i++) {
        const int row = wm * 32 + i * 16 + (seg & 1) * 8 + rr;
        aoff[i] = (uint32_t)((row * AST + (seg >> 1) * 8) * 2);
    }
#pragma unroll
    for (int j = 0; j < 2; j++) {
        const int nrow = wn * 32 + j * 16 + ((seg >> 1) ? 8 : 0) + rr;
        boff[j] = (uint32_t)((nrow * AST + (seg & 1) * 8) * 2);
    }

    // per-thread load coords
    const int lrowA = tid >> 2;              // 0..63 (x2 halves)
    const int lc8   = (tid & 3) * 8;         // 0,8,16,24
    const uint32_t soA = (uint32_t)((lrowA * AST + lc8) * 2);
    const uint32_t soA2 = (uint32_t)(((lrowA + 64) * AST + lc8) * 2);
    const uint32_t soB = soA;

    float acc[2][4][4];
#pragma unroll
    for (int i = 0; i < 2; i++)
#pragma unroll
        for (int j = 0; j < 4; j++)
#pragma unroll
            for (int q = 0; q < 4; q++) acc[i][j][q] = 0.f;

    const int nch = K >> 5;     // K/32

    // stage loader
    auto load_stage = [&](int kt, int s) {
        const int kc = kt << 5;
        const uint32_t st = sb + s * SSTR;
        size_t gi = (size_t)(m0 + lrowA) * K + kc + lc8;
        CP16(st + soA, Ahi + gi);
        CP16(st + OFF_AL + soA, Alo + gi);
        gi = (size_t)(m0 + 64 + lrowA) * K + kc + lc8;
        CP16(st + soA2, Ahi + gi);
        CP16(st + OFF_AL + soA2, Alo + gi);
        gi = (size_t)(n0 + lrowA) * K + kc + lc8;
        CP16(st + OFF_BH + soB, Bhi + gi);
        CP16(st + OFF_BL + soB, Blo + gi);
    };

    load_stage(0, 0);
    CP_COMMIT();

    for (int kt = 0; kt < nch; kt++) {
        const int s = kt & 1;
        if (kt + 1 < nch) load_stage(kt + 1, s ^ 1);
        CP_COMMIT();
        CP_WAIT1();
        __syncthreads();

        const uint32_t st = sb + s * SSTR;
#pragma unroll
        for (int kk = 0; kk < 2; kk++) {
            const uint32_t kb = kk * 32;   // 16 bf16 = 32 bytes
            uint32_t ah[2][4], al[2][4], bh[2][4], bl[2][4];
#pragma unroll
            for (int i = 0; i < 2; i++) {
                ldm_x4(ah[i], st + aoff[i] + kb);
                ldm_x4(al[i], st + OFF_AL + aoff[i] + kb);
            }
#pragma unroll
            for (int j = 0; j < 2; j++) {
                ldm_x4(bh[j], st + OFF_BH + boff[j] + kb);
                ldm_x4(bl[j], st + OFF_BL + boff[j] + kb);
            }
#pragma unroll
            for (int i = 0; i < 2; i++) {
#pragma unroll
                for (int jt = 0; jt < 4; jt++) {
                    const int j = jt >> 1;
                    const int po = (jt & 1) * 2;
                    uint32_t bhp[2] = { bh[j][po], bh[j][po + 1] };
                    uint32_t blp[2] = { bl[j][po], bl[j][po + 1] };
                    mma_bf16(acc[i][jt], ah[i], bhp);
                    mma_bf16(acc[i][jt], ah[i], blp);
                    mma_bf16(acc[i][jt], al[i], bhp);
                }
            }
        }
        __syncthreads();
    }

    // -------- epilogue --------
    const int tg = lane >> 2;        // row-in-8
    const int t4 = lane & 3;         // col pair group

    // region dispatch for EPI==4
    int region = 0;
    const float* bptr = bias;
    float* optr = C;
    int oldN = N;
    int colbase = n0;
    if (EPI == 4) {
        if (n0 < 256)      { region = 0; bptr = bias;  optr = C;  oldN = 256; colbase = n0; }
        else if (n0 < 512) { region = 1; bptr = bias2; optr = C2; oldN = 256; colbase = n0 - 256; }
        else               { region = 2; bptr = bias3; optr = C3; oldN = 128; colbase = n0 - 512; }
    }

#pragma unroll
    for (int i = 0; i < 2; i++) {
#pragma unroll
        for (int jt = 0; jt < 4; jt++) {
            const int colg = colbase + wn * 32 + jt * 8 + t4 * 2;  // even col, 2 wide
            const float b0 = bptr[colg];
            const float b1 = bptr[colg + 1];
#pragma unroll
            for (int half = 0; half < 2; half++) {
                const int row = m0 + wm * 32 + i * 16 + tg + half * 8;
                float v0 = acc[i][jt][half * 2 + 0] + b0;
                float v1 = acc[i][jt][half * 2 + 1] + b1;
                if (EPI == 4 && region == 1) {
                    const int l = (colg >> 3) & 3;
                    const float r0 = ref[(size_t)row * 8 + l * 2 + 0];
                    const float r1 = ref[(size_t)row * 8 + l * 2 + 1];
                    v0 = v0 * (1.f / 32.f) + r0;
                    v1 = v1 * (1.f / 32.f) + r1;
                } else if (EPI == 3) {
                    const float2 rv = *(const float2*)(res + (size_t)row * N + colg);
                    v0 += rv.x; v1 += rv.y;
                }
                if (EPI == 2) {
                    v0 = fmaxf(v0, 0.f);
                    v1 = fmaxf(v1, 0.f);
                    const __nv_bfloat16 h0 = __float2bfloat16(v0);
                    const __nv_bfloat16 h1 = __float2bfloat16(v1);
                    __nv_bfloat162 hp, lp;
                    hp.x = h0; hp.y = h1;
                    lp.x = __float2bfloat16(v0 - __bfloat162float(h0));
                    lp.y = __float2bfloat16(v1 - __bfloat162float(h1));
                    *(__nv_bfloat162*)(Chi + (size_t)row * N + colg) = hp;
                    *(__nv_bfloat162*)(Clo + (size_t)row * N + colg) = lp;
                } else {
                    float2 o; o.x = v0; o.y = v1;
                    *(float2*)(optr + (size_t)row * oldN + colg) = o;
                }
            }
        }
    }
}

// ---------------- fp32 -> hi/lo bf16 elementwise ----------------
__global__ void conv_hl_kernel(const float* __restrict__ x,
                               __nv_bfloat16* __restrict__ h, __nv_bfloat16* __restrict__ l,
                               int n)
{
    const int i = blockIdx.x * blockDim.x + threadIdx.x;
    if (i >= n) return;
    const float v = x[i];
    const __nv_bfloat16 hv = __float2bfloat16(v);
    h[i] = hv;
    l[i] = __float2bfloat16(v - __bfloat162float(hv));
}

// ---------------- all-weights transpose + split in one launch --------------
__global__ void prep_all_kernel(const float* __restrict__ vp, const float* __restrict__ so,
                                const float* __restrict__ awW, const float* __restrict__ op,
                                const float* __restrict__ l1, const float* __restrict__ l2,
                                __nv_bfloat16* __restrict__ h, __nv_bfloat16* __restrict__ l)
{
    const int i = blockIdx.x * blockDim.x + threadIdx.x;
    if (i >= W_TOTAL) return;
    const float* W;
    int K, N, base;
    if      (i < WOFF_SO) { W = vp;  K = 256;  N = 256;  base = WOFF_VP; }
    else if (i < WOFF_AW) { W = so;  K = 256;  N = 256;  base = WOFF_SO; }
    else if (i < WOFF_OP) { W = awW; K = 256;  N = 128;  base = WOFF_AW; }
    else if (i < WOFF_L1) { W = op;  K = 256;  N = 256;  base = WOFF_OP; }
    else if (i < WOFF_L2) { W = l1;  K = 256;  N = 1024; base = WOFF_L1; }
    else                  { W = l2;  K = 1024; N = 256;  base = WOFF_L2; }
    const int li = i - base;
    const int n = li / K;
    const int k = li - n * K;
    const float v = W[(size_t)k * N + n];
    const __nv_bfloat16 hv = __float2bfloat16(v);
    h[i] = hv;
    l[i] = __float2bfloat16(v - __bfloat162float(hv));
}

// ---------------- deformable gather with fused softmax; emits hi/lo bf16 ---
__global__ __launch_bounds__(256)
void gather_kernel(const float* __restrict__ value, const float* __restrict__ slocs,
                   const float* __restrict__ logits,
                   __nv_bfloat16* __restrict__ outh, __nv_bfloat16* __restrict__ outl)
{
    const int m = blockIdx.x;
    const int h = threadIdx.x >> 5;
    const int d = threadIdx.x & 31;
    const int b = m >> 12;

    const float* sl = slocs + (((size_t)m * NH + h) * NL * NP) * 2;
    const float* lg = logits + (size_t)m * 128 + h * 16;

    // fused softmax over 16 (redundant per lane; broadcast loads)
    float w[16];
    float mx = -1e30f;
#pragma unroll
    for (int i = 0; i < 16; i++) { w[i] = lg[i]; mx = fmaxf(mx, w[i]); }
    float ssum = 0.f;
#pragma unroll
    for (int i = 0; i < 16; i++) { w[i] = __expf(w[i] - mx); ssum += w[i]; }
    const float sinv = 1.f / ssum;

    float acc = 0.f;
#pragma unroll
    for (int l = 0; l < NL; l++) {
        const size_t vbase = ((size_t)b * LQ + (size_t)l * HW);
#pragma unroll
        for (int p = 0; p < NP; p++) {
            const int s = l * NP + p;
            const float x = sl[2 * s]     * (float)WS - 0.5f;
            const float y = sl[2 * s + 1] * (float)HS - 0.5f;
            const float ww = w[s] * sinv;
            const float x0f = floorf(x);
            const float y0f = floorf(y);
            const int x0 = (int)x0f;
            const int y0 = (int)y0f;
            const float lx = x - x0f;
            const float ly = y - y0f;
#pragma unroll
            for (int dy = 0; dy < 2; dy++) {
                const int yi = y0 + dy;
                if (yi < 0 || yi >= HS) continue;
                const float wy = dy ? ly : (1.f - ly);
#pragma unroll
                for (int dx = 0; dx < 2; dx++) {
                    const int xi = x0 + dx;
                    if (xi < 0 || xi >= WS) continue;
                    const float wx = dx ? lx : (1.f - lx);
                    const size_t vrow = vbase + (size_t)yi * WS + xi;
                    acc = fmaf(ww * wy * wx, value[(vrow * NH + h) * HD + d], acc);
                }
            }
        }
    }
    const size_t oi = (size_t)m * D_ + h * HD + d;
    const __nv_bfloat16 hv = __float2bfloat16(acc);
    outh[oi] = hv;
    outl[oi] = __float2bfloat16(acc - __bfloat162float(hv));
}

// ---------------- layernorm over 256 cols; one warp per row ----------------
template<int MODE>
__global__ __launch_bounds__(256)
void layernorm_kernel(const float* __restrict__ in, const float* __restrict__ g,
                      const float* __restrict__ b, float* __restrict__ out,
                      __nv_bfloat16* __restrict__ outh, __nv_bfloat16* __restrict__ outl)
{
    const int row = blockIdx.x * 8 + (threadIdx.x >> 5);
    const int lane = threadIdx.x & 31;
    const float* r = in + (size_t)row * D_;
    float v[8];
    float s = 0.f, s2 = 0.f;
#pragma unroll
    for (int i = 0; i < 8; i++) {
        v[i] = r[i * 32 + lane];
        s += v[i];
        s2 = fmaf(v[i], v[i], s2);
    }
#pragma unroll
    for (int o = 16; o > 0; o >>= 1) {
        s  += __shfl_xor_sync(0xffffffff, s, o);
        s2 += __shfl_xor_sync(0xffffffff, s2, o);
    }
    const float mean = s * (1.f / 256.f);
    const float var  = s2 * (1.f / 256.f) - mean * mean;
    const float inv  = rsqrtf(var + 1e-5f);
#pragma unroll
    for (int i = 0; i < 8; i++) {
        const int c = i * 32 + lane;
        const float u = (v[i] - mean) * inv * g[c] + b[c];
        out[(size_t)row * D_ + c] = u;
        if (MODE == 1) {
            const __nv_bfloat16 hv = __float2bfloat16(u);
            outh[(size_t)row * D_ + c] = hv;
            outl[(size_t)row * D_ + c] = __float2bfloat16(u - __bfloat162float(hv));
        }
    }
}

// ---------------- host launch ----------------
extern "C" void kernel_launch(void* const* d_in, const int* in_sizes, int n_in,
                              void* d_out, int out_size)
{
    const float* src    = (const float*)d_in[0];
    // d_in[1] = pos (unused by the reference forward)
    const float* refpts = (const float*)d_in[2];
    const float* vp_w   = (const float*)d_in[3];
    const float* vp_b   = (const float*)d_in[4];
    const float* so_w   = (const float*)d_in[5];
    const float* so_b   = (const float*)d_in[6];
    const float* aw_w   = (const float*)d_in[7];
    const float* aw_b   = (const float*)d_in[8];
    const float* op_w   = (const float*)d_in[9];
    const float* op_b   = (const float*)d_in[10];
    const float* n1_g   = (const float*)d_in[11];
    const float* n1_b   = (const float*)d_in[12];
    const float* l1_w   = (const float*)d_in[13];
    const float* l1_b   = (const float*)d_in[14];
    const float* l2_w   = (const float*)d_in[15];
    const float* l2_b   = (const float*)d_in[16];
    const float* n2_g   = (const float*)d_in[17];
    const float* n2_b   = (const float*)d_in[18];

    float* out_x = (float*)d_out;
    float* slocs = (float*)d_out + X_ELEMS;

    __nv_bfloat16 *src_h, *src_l, *w_h, *w_l, *attn_h, *attn_l, *x1_h, *x1_l, *ffn_h, *ffn_l;
    float *value, *aw, *tmpf, *x1;
    cudaGetSymbolAddress((void**)&src_h, g_src_h);
    cudaGetSymbolAddress((void**)&src_l, g_src_l);
    cudaGetSymbolAddress((void**)&w_h,   g_w_h);
    cudaGetSymbolAddress((void**)&w_l,   g_w_l);
    cudaGetSymbolAddress((void**)&value, g_value);
    cudaGetSymbolAddress((void**)&aw,    g_aw);
    cudaGetSymbolAddress((void**)&attn_h, g_attn_h);
    cudaGetSymbolAddress((void**)&attn_l, g_attn_l);
    cudaGetSymbolAddress((void**)&tmpf,  g_tmpf);
    cudaGetSymbolAddress((void**)&x1,    g_x1);
    cudaGetSymbolAddress((void**)&x1_h,  g_x1_h);
    cudaGetSymbolAddress((void**)&x1_l,  g_x1_l);
    cudaGetSymbolAddress((void**)&ffn_h, g_ffn_h);
    cudaGetSymbolAddress((void**)&ffn_l, g_ffn_l);

    cudaFuncSetAttribute(mma_gemm<2>, cudaFuncAttributeMaxDynamicSharedMemorySize, SMEM_TOT);
    cudaFuncSetAttribute(mma_gemm<3>, cudaFuncAttributeMaxDynamicSharedMemorySize, SMEM_TOT);
    cudaFuncSetAttribute(mma_gemm<4>, cudaFuncAttributeMaxDynamicSharedMemorySize, SMEM_TOT);

    // 0) conversions (2 launches)
    conv_hl_kernel<<<(M_TOK * D_ + 255) / 256, 256>>>(src, src_h, src_l, M_TOK * D_);
    prep_all_kernel<<<(W_TOTAL + 255) / 256, 256>>>(vp_w, so_w, aw_w, op_w, l1_w, l2_w, w_h, w_l);

    const dim3 blk(256);
    const dim3 gfused(640 / 64, M_TOK / 128);  // (10, 64) = 640 CTAs
    const dim3 g256(256 / 64, M_TOK / 128);    // (4, 64)
    const dim3 g1024(1024 / 64, M_TOK / 128);  // (16, 64)

    // 1) fused: value | sampling_locations | attn logits
    mma_gemm<4><<<gfused, blk, SMEM_TOT>>>(src_h, src_l, w_h, w_l,
                                           vp_b, so_b, aw_b, nullptr, refpts,
                                           value, slocs, aw, nullptr, nullptr, 640, 256);
    // 2) gather (softmax fused) -> attn hi/lo
    gather_kernel<<<M_TOK, 256>>>(value, slocs, aw, attn_h, attn_l);
    // 3) out_proj + residual(src) -> tmpf
    mma_gemm<3><<<g256, blk, SMEM_TOT>>>(attn_h, attn_l, w_h + WOFF_OP, w_l + WOFF_OP,
                                         op_b, nullptr, nullptr, src, nullptr,
                                         tmpf, nullptr, nullptr, nullptr, nullptr, 256, 256);
    // 4) LN1 -> x1 (fp32 + hi/lo)
    layernorm_kernel<1><<<M_TOK / 8, 256>>>(tmpf, n1_g, n1_b, x1, x1_h, x1_l);
    // 5) FFN1: relu -> ffn hi/lo
    mma_gemm<2><<<g1024, blk, SMEM_TOT>>>(x1_h, x1_l, w_h + WOFF_L1, w_l + WOFF_L1,
                                          l1_b, nullptr, nullptr, nullptr, nullptr,
                                          nullptr, nullptr, nullptr, ffn_h, ffn_l, 1024, 256);
    // 6) FFN2 + residual(x1) -> tmpf
    mma_gemm<3><<<g256, blk, SMEM_TOT>>>(ffn_h, ffn_l, w_h + WOFF_L2, w_l + WOFF_L2,
                                         l2_b, nullptr, nullptr, x1, nullptr,
                                         tmpf, nullptr, nullptr, nullptr, nullptr, 256, 1024);
    // 7) LN2 -> final output
    layernorm_kernel<0><<<M_TOK / 8, 256>>>(tmpf, n2_g, n2_b, out_x, nullptr, nullptr);
}

// round 12
// speedup vs baseline: 2.3520x; 1.2120x over previous
#include <cuda_runtime.h>
#include <cuda_bf16.h>
#include <math.h>
#include <stdint.h>

// Problem constants (fixed by the reference setup)
#define BS   2
#define T_   4
#define HS   32
#define WS   32
#define HW   (HS*WS)          // 1024
#define LQ   (T_*HW)          // 4096
#define M_TOK (BS*LQ)         // 8192 rows
#define D_   256
#define NH   8
#define NL   4
#define NP   4
#define HD   32               // D/NH
#define DFFN 1024
#define X_ELEMS   (BS*LQ*D_)              // 2097152 (output x)

// ---------------- scratch (no allocations allowed) ----------------
__device__ __nv_bfloat16 g_src_h[M_TOK * D_];
__device__ __nv_bfloat16 g_src_l[M_TOK * D_];
// transposed weights [N][K], hi/lo; fused layout: vp | so | aw | op | l1 | l2
#define WOFF_VP 0
#define WOFF_SO 65536
#define WOFF_AW 131072
#define WOFF_OP 163840
#define WOFF_L1 229376
#define WOFF_L2 491520
#define W_TOTAL 753664
__device__ __nv_bfloat16 g_w_h[W_TOTAL];
__device__ __nv_bfloat16 g_w_l[W_TOTAL];

__device__ float g_value[M_TOK * D_];        // value fp32 for gather
__device__ float g_aw[M_TOK * 128];          // attention LOGITS (softmax fused in gather)
__device__ __nv_bfloat16 g_attn_h[M_TOK * D_];
__device__ __nv_bfloat16 g_attn_l[M_TOK * D_];
__device__ float g_tmpf[M_TOK * D_];         // pre-LN buffer (reused)
__device__ float g_x1[M_TOK * D_];           // after LN1
__device__ __nv_bfloat16 g_x1_h[M_TOK * D_];
__device__ __nv_bfloat16 g_x1_l[M_TOK * D_];
__device__ __nv_bfloat16 g_ffn_h[M_TOK * DFFN];
__device__ __nv_bfloat16 g_ffn_l[M_TOK * DFFN];

// ---------------- warp MMA helpers (baseline PTX, no 'a' features) --------
__device__ __forceinline__ uint32_t smem_u32(const void* p) {
    uint32_t a;
    asm("{ .reg .u64 t; cvta.to.shared.u64 t, %1; cvt.u32.u64 %0, t; }" : "=r"(a) : "l"(p));
    return a;
}
__device__ __forceinline__ void ldm_x4(uint32_t* r, uint32_t addr) {
    asm volatile("ldmatrix.sync.aligned.m8n8.x4.shared.b16 {%0,%1,%2,%3}, [%4];"
                 : "=r"(r[0]), "=r"(r[1]), "=r"(r[2]), "=r"(r[3]) : "r"(addr));
}
__device__ __forceinline__ void mma_bf16(float* c, const uint32_t* a, const uint32_t* b) {
    asm volatile("mma.sync.aligned.m16n8k16.row.col.f32.bf16.bf16.f32 "
                 "{%0,%1,%2,%3}, {%4,%5,%6,%7}, {%8,%9}, {%0,%1,%2,%3};"
                 : "+f"(c[0]), "+f"(c[1]), "+f"(c[2]), "+f"(c[3])
                 : "r"(a[0]), "r"(a[1]), "r"(a[2]), "r"(a[3]), "r"(b[0]), "r"(b[1]));
}
#define CP16(dst, src) \
    asm volatile("cp.async.cg.shared.global [%0], [%1], 16;" :: "r"(dst), "l"(src))
#define CP_COMMIT() asm volatile("cp.async.commit_group;" ::: "memory")
#define CP_WAIT1()  asm volatile("cp.async.wait_group 1;"  ::: "memory")

// ---------------- bf16x3 tensor GEMM via mma.sync + cp.async pipeline ------
// EPI: 2 = relu -> hi/lo bf16   3 = +bias+res (fp32)
//      4 = fused src-projections: region by n0: [0,256)=value fp32,
//          [256,512)=sampling-loc, [512,640)=attn logits
#define AST 40                    // smem row stride (bf16): 80B rows, 16B aligned
#define SSTR 30720                // bytes per pipeline stage
#define OFF_AL 10240
#define OFF_BH 20480
#define OFF_BL 25600
#define SMEM_TOT (2 * SSTR)       // 61440 B dynamic smem

template<int EPI>
__global__ __launch_bounds__(256)
void mma_gemm(const __nv_bfloat16* __restrict__ Ahi, const __nv_bfloat16* __restrict__ Alo,
              const __nv_bfloat16* __restrict__ Bhi, const __nv_bfloat16* __restrict__ Blo,
              const float* __restrict__ bias, const float* __restrict__ bias2,
              const float* __restrict__ bias3,
              const float* __restrict__ res, const float* __restrict__ ref,
              float* __restrict__ C, float* __restrict__ C2, float* __restrict__ C3,
              __nv_bfloat16* __restrict__ Chi, __nv_bfloat16* __restrict__ Clo,
              int N, int K)
{
    extern __shared__ char smem[];
    const uint32_t sb = smem_u32(smem);

    const int tid  = threadIdx.x;
    const int wid  = tid >> 5;
    const int lane = tid & 31;
    const int wm   = wid >> 1;          // 0..3  (M dir, 32 rows each)
    const int wn   = wid & 1;           // 0..1  (N dir, 32 cols each)
    const int m0   = blockIdx.y * 128;
    const int n0   = blockIdx.x * 64;

    const int seg = lane >> 3;
    const int rr  = lane & 7;

    uint32_t aoff[2], boff[2];
#pragma unroll
    for (int i = 0; i < 2; i++) {
        const int row = wm * 32 + i * 16 + (seg & 1) * 8 + rr;
        aoff[i] = (uint32_t)((row * AST + (seg >> 1) * 8) * 2);
    }
#pragma unroll
    for (int j = 0; j < 2; j++) {
        const int nrow = wn * 32 + j * 16 + ((seg >> 1) ? 8 : 0) + rr;
        boff[j] = (uint32_t)((nrow * AST + (seg & 1) * 8) * 2);
    }

    // per-thread load coords
    const int lrowA = tid >> 2;              // 0..63 (x2 halves)
    const int lc8   = (tid & 3) * 8;         // 0,8,16,24
    const uint32_t soA = (uint32_t)((lrowA * AST + lc8) * 2);
    const uint32_t soA2 = (uint32_t)(((lrowA + 64) * AST + lc8) * 2);
    const uint32_t soB = soA;

    float acc[2][4][4];
#pragma unroll
    for (int i = 0; i < 2; i++)
#pragma unroll
        for (int j = 0; j < 4; j++)
#pragma unroll
            for (int q = 0; q < 4; q++) acc[i][j][q] = 0.f;

    const int nch = K >> 5;     // K/32

    auto load_stage = [&](int kt, int s) {
        const int kc = kt << 5;
        const uint32_t st = sb + s * SSTR;
        size_t gi = (size_t)(m0 + lrowA) * K + kc + lc8;
        CP16(st + soA, Ahi + gi);
        CP16(st + OFF_AL + soA, Alo + gi);
        gi = (size_t)(m0 + 64 + lrowA) * K + kc + lc8;
        CP16(st + soA2, Ahi + gi);
        CP16(st + OFF_AL + soA2, Alo + gi);
        gi = (size_t)(n0 + lrowA) * K + kc + lc8;
        CP16(st + OFF_BH + soB, Bhi + gi);
        CP16(st + OFF_BL + soB, Blo + gi);
    };

    load_stage(0, 0);
    CP_COMMIT();

    for (int kt = 0; kt < nch; kt++) {
        const int s = kt & 1;
        if (kt + 1 < nch) load_stage(kt + 1, s ^ 1);
        CP_COMMIT();
        CP_WAIT1();
        __syncthreads();

        const uint32_t st = sb + s * SSTR;
#pragma unroll
        for (int kk = 0; kk < 2; kk++) {
            const uint32_t kb = kk * 32;   // 16 bf16 = 32 bytes
            uint32_t ah[2][4], al[2][4], bh[2][4], bl[2][4];
#pragma unroll
            for (int i = 0; i < 2; i++) {
                ldm_x4(ah[i], st + aoff[i] + kb);
                ldm_x4(al[i], st + OFF_AL + aoff[i] + kb);
            }
#pragma unroll
            for (int j = 0; j < 2; j++) {
                ldm_x4(bh[j], st + OFF_BH + boff[j] + kb);
                ldm_x4(bl[j], st + OFF_BL + boff[j] + kb);
            }
#pragma unroll
            for (int i = 0; i < 2; i++) {
#pragma unroll
                for (int jt = 0; jt < 4; jt++) {
                    const int j = jt >> 1;
                    const int po = (jt & 1) * 2;
                    uint32_t bhp[2] = { bh[j][po], bh[j][po + 1] };
                    uint32_t blp[2] = { bl[j][po], bl[j][po + 1] };
                    mma_bf16(acc[i][jt], ah[i], bhp);
                    mma_bf16(acc[i][jt], ah[i], blp);
                    mma_bf16(acc[i][jt], al[i], bhp);
                }
            }
        }
        __syncthreads();
    }

    // -------- epilogue --------
    const int tg = lane >> 2;        // row-in-8
    const int t4 = lane & 3;         // col pair group

    int region = 0;
    const float* bptr = bias;
    float* optr = C;
    int oldN = N;
    int colbase = n0;
    if (EPI == 4) {
        if (n0 < 256)      { region = 0; bptr = bias;  optr = C;  oldN = 256; colbase = n0; }
        else if (n0 < 512) { region = 1; bptr = bias2; optr = C2; oldN = 256; colbase = n0 - 256; }
        else               { region = 2; bptr = bias3; optr = C3; oldN = 128; colbase = n0 - 512; }
    }

#pragma unroll
    for (int i = 0; i < 2; i++) {
#pragma unroll
        for (int jt = 0; jt < 4; jt++) {
            const int colg = colbase + wn * 32 + jt * 8 + t4 * 2;  // even col, 2 wide
            const float b0 = bptr[colg];
            const float b1 = bptr[colg + 1];
#pragma unroll
            for (int half = 0; half < 2; half++) {
                const int row = m0 + wm * 32 + i * 16 + tg + half * 8;
                float v0 = acc[i][jt][half * 2 + 0] + b0;
                float v1 = acc[i][jt][half * 2 + 1] + b1;
                if (EPI == 4 && region == 1) {
                    const int l = (colg >> 3) & 3;
                    const float r0 = ref[(size_t)row * 8 + l * 2 + 0];
                    const float r1 = ref[(size_t)row * 8 + l * 2 + 1];
                    v0 = v0 * (1.f / 32.f) + r0;
                    v1 = v1 * (1.f / 32.f) + r1;
                } else if (EPI == 3) {
                    const float2 rv = *(const float2*)(res + (size_t)row * N + colg);
                    v0 += rv.x; v1 += rv.y;
                }
                if (EPI == 2) {
                    v0 = fmaxf(v0, 0.f);
                    v1 = fmaxf(v1, 0.f);
                    const __nv_bfloat16 h0 = __float2bfloat16(v0);
                    const __nv_bfloat16 h1 = __float2bfloat16(v1);
                    __nv_bfloat162 hp, lp;
                    hp.x = h0; hp.y = h1;
                    lp.x = __float2bfloat16(v0 - __bfloat162float(h0));
                    lp.y = __float2bfloat16(v1 - __bfloat162float(h1));
                    *(__nv_bfloat162*)(Chi + (size_t)row * N + colg) = hp;
                    *(__nv_bfloat162*)(Clo + (size_t)row * N + colg) = lp;
                } else {
                    float2 o; o.x = v0; o.y = v1;
                    *(float2*)(optr + (size_t)row * oldN + colg) = o;
                }
            }
        }
    }
}

// ---------------- fp32 -> hi/lo bf16 elementwise ----------------
__global__ void conv_hl_kernel(const float* __restrict__ x,
                               __nv_bfloat16* __restrict__ h, __nv_bfloat16* __restrict__ l,
                               int n)
{
    const int i = blockIdx.x * blockDim.x + threadIdx.x;
    if (i >= n) return;
    const float v = x[i];
    const __nv_bfloat16 hv = __float2bfloat16(v);
    h[i] = hv;
    l[i] = __float2bfloat16(v - __bfloat162float(hv));
}

// ---------------- all-weights transpose + split in one launch --------------
__global__ void prep_all_kernel(const float* __restrict__ vp, const float* __restrict__ so,
                                const float* __restrict__ awW, const float* __restrict__ op,
                                const float* __restrict__ l1, const float* __restrict__ l2,
                                __nv_bfloat16* __restrict__ h, __nv_bfloat16* __restrict__ l)
{
    const int i = blockIdx.x * blockDim.x + threadIdx.x;
    if (i >= W_TOTAL) return;
    const float* W;
    int K, N, base;
    if      (i < WOFF_SO) { W = vp;  K = 256;  N = 256;  base = WOFF_VP; }
    else if (i < WOFF_AW) { W = so;  K = 256;  N = 256;  base = WOFF_SO; }
    else if (i < WOFF_OP) { W = awW; K = 256;  N = 128;  base = WOFF_AW; }
    else if (i < WOFF_L1) { W = op;  K = 256;  N = 256;  base = WOFF_OP; }
    else if (i < WOFF_L2) { W = l1;  K = 256;  N = 1024; base = WOFF_L1; }
    else                  { W = l2;  K = 1024; N = 256;  base = WOFF_L2; }
    const int li = i - base;
    const int n = li / K;
    const int k = li - n * K;
    const float v = W[(size_t)k * N + n];
    const __nv_bfloat16 hv = __float2bfloat16(v);
    h[i] = hv;
    l[i] = __float2bfloat16(v - __bfloat162float(hv));
}

// ---------------- deformable gather: 3-phase, de-duplicated scalar work ----
// Block = one token m (8 warps = 8 heads).
// P0: 8 threads softmax the 16 logits of their head -> s_w
// P1: 128 threads (one per head,sample) compute 4 corner weights*w + indices
// P2: each warp does 16 x (2 LDS.128 broadcast + 4 LDG + 4 FFMA)
__global__ __launch_bounds__(256)
void gather_kernel(const float* __restrict__ value, const float* __restrict__ slocs,
                   const float* __restrict__ logits,
                   __nv_bfloat16* __restrict__ outh, __nv_bfloat16* __restrict__ outl)
{
    __shared__ float s_w[128];
    __shared__ float s_cw[128 * 4];
    __shared__ int   s_ci[128 * 4];

    const int m = blockIdx.x;
    const int tid = threadIdx.x;
    const int b = m >> 12;

    if (tid < 8) {
        const float* lg = logits + (size_t)m * 128 + tid * 16;
        float w[16];
        float mx = -1e30f;
#pragma unroll
        for (int i = 0; i < 16; i++) { w[i] = lg[i]; mx = fmaxf(mx, w[i]); }
        float ssum = 0.f;
#pragma unroll
        for (int i = 0; i < 16; i++) { w[i] = __expf(w[i] - mx); ssum += w[i]; }
        const float sinv = 1.f / ssum;
#pragma unroll
        for (int i = 0; i < 16; i++) s_w[tid * 16 + i] = w[i] * sinv;
    }
    __syncthreads();

    if (tid < 128) {
        const int h = tid >> 4;
        const int s = tid & 15;
        const int l = s >> 2;
        const float* sl = slocs + (((size_t)m * NH + h) * 16 + s) * 2;
        const float x = sl[0] * (float)WS - 0.5f;
        const float y = sl[1] * (float)HS - 0.5f;
        const float ww = s_w[tid];
        const float x0f = floorf(x);
        const float y0f = floorf(y);
        const int x0 = (int)x0f;
        const int y0 = (int)y0f;
        const float lx = x - x0f;
        const float ly = y - y0f;
        const int vbase = b * LQ + l * HW;
#pragma unroll
        for (int dy = 0; dy < 2; dy++) {
            const int yi = y0 + dy;
            const float wy = dy ? ly : (1.f - ly);
#pragma unroll
            for (int dx = 0; dx < 2; dx++) {
                const int xi = x0 + dx;
                const float wx = dx ? lx : (1.f - lx);
                const bool valid = (yi >= 0) & (yi < HS) & (xi >= 0) & (xi < WS);
                const int yc = min(max(yi, 0), HS - 1);
                const int xc = min(max(xi, 0), WS - 1);
                const int ci = tid * 4 + dy * 2 + dx;
                s_cw[ci] = valid ? (ww * wy * wx) : 0.f;
                s_ci[ci] = vbase + yc * WS + xc;
            }
        }
    }
    __syncthreads();

    const int h = tid >> 5;
    const int d = tid & 31;
    const int hb = h * HD + d;
    float acc = 0.f;
#pragma unroll
    for (int s = 0; s < 16; s++) {
        const int si = (h * 16 + s) * 4;
        const float4 cw = *(const float4*)&s_cw[si];
        const int4   ci = *(const int4*)&s_ci[si];
        acc = fmaf(cw.x, value[(size_t)ci.x * D_ + hb], acc);
        acc = fmaf(cw.y, value[(size_t)ci.y * D_ + hb], acc);
        acc = fmaf(cw.z, value[(size_t)ci.z * D_ + hb], acc);
        acc = fmaf(cw.w, value[(size_t)ci.w * D_ + hb], acc);
    }
    const size_t oi = (size_t)m * D_ + hb;
    const __nv_bfloat16 hv = __float2bfloat16(acc);
    outh[oi] = hv;
    outl[oi] = __float2bfloat16(acc - __bfloat162float(hv));
}

// ---------------- layernorm over 256 cols; one warp per row ----------------
template<int MODE>
__global__ __launch_bounds__(256)
void layernorm_kernel(const float* __restrict__ in, const float* __restrict__ g,
                      const float* __restrict__ b, float* __restrict__ out,
                      __nv_bfloat16* __restrict__ outh, __nv_bfloat16* __restrict__ outl)
{
    const int row = blockIdx.x * 8 + (threadIdx.x >> 5);
    const int lane = threadIdx.x & 31;
    const float* r = in + (size_t)row * D_;
    float v[8];
    float s = 0.f, s2 = 0.f;
#pragma unroll
    for (int i = 0; i < 8; i++) {
        v[i] = r[i * 32 + lane];
        s += v[i];
        s2 = fmaf(v[i], v[i], s2);
    }
#pragma unroll
    for (int o = 16; o > 0; o >>= 1) {
        s  += __shfl_xor_sync(0xffffffff, s, o);
        s2 += __shfl_xor_sync(0xffffffff, s2, o);
    }
    const float mean = s * (1.f / 256.f);
    const float var  = s2 * (1.f / 256.f) - mean * mean;
    const float inv  = rsqrtf(var + 1e-5f);
#pragma unroll
    for (int i = 0; i < 8; i++) {
        const int c = i * 32 + lane;
        const float u = (v[i] - mean) * inv * g[c] + b[c];
        out[(size_t)row * D_ + c] = u;
        if (MODE == 1) {
            const __nv_bfloat16 hv = __float2bfloat16(u);
            outh[(size_t)row * D_ + c] = hv;
            outl[(size_t)row * D_ + c] = __float2bfloat16(u - __bfloat162float(hv));
        }
    }
}

// ---------------- host launch ----------------
extern "C" void kernel_launch(void* const* d_in, const int* in_sizes, int n_in,
                              void* d_out, int out_size)
{
    const float* src    = (const float*)d_in[0];
    // d_in[1] = pos (unused by the reference forward)
    const float* refpts = (const float*)d_in[2];
    const float* vp_w   = (const float*)d_in[3];
    const float* vp_b   = (const float*)d_in[4];
    const float* so_w   = (const float*)d_in[5];
    const float* so_b   = (const float*)d_in[6];
    const float* aw_w   = (const float*)d_in[7];
    const float* aw_b   = (const float*)d_in[8];
    const float* op_w   = (const float*)d_in[9];
    const float* op_b   = (const float*)d_in[10];
    const float* n1_g   = (const float*)d_in[11];
    const float* n1_b   = (const float*)d_in[12];
    const float* l1_w   = (const float*)d_in[13];
    const float* l1_b   = (const float*)d_in[14];
    const float* l2_w   = (const float*)d_in[15];
    const float* l2_b   = (const float*)d_in[16];
    const float* n2_g   = (const float*)d_in[17];
    const float* n2_b   = (const float*)d_in[18];

    float* out_x = (float*)d_out;
    float* slocs = (float*)d_out + X_ELEMS;

    __nv_bfloat16 *src_h, *src_l, *w_h, *w_l, *attn_h, *attn_l, *x1_h, *x1_l, *ffn_h, *ffn_l;
    float *value, *aw, *tmpf, *x1;
    cudaGetSymbolAddress((void**)&src_h, g_src_h);
    cudaGetSymbolAddress((void**)&src_l, g_src_l);
    cudaGetSymbolAddress((void**)&w_h,   g_w_h);
    cudaGetSymbolAddress((void**)&w_l,   g_w_l);
    cudaGetSymbolAddress((void**)&value, g_value);
    cudaGetSymbolAddress((void**)&aw,    g_aw);
    cudaGetSymbolAddress((void**)&attn_h, g_attn_h);
    cudaGetSymbolAddress((void**)&attn_l, g_attn_l);
    cudaGetSymbolAddress((void**)&tmpf,  g_tmpf);
    cudaGetSymbolAddress((void**)&x1,    g_x1);
    cudaGetSymbolAddress((void**)&x1_h,  g_x1_h);
    cudaGetSymbolAddress((void**)&x1_l,  g_x1_l);
    cudaGetSymbolAddress((void**)&ffn_h, g_ffn_h);
    cudaGetSymbolAddress((void**)&ffn_l, g_ffn_l);

    cudaFuncSetAttribute(mma_gemm<2>, cudaFuncAttributeMaxDynamicSharedMemorySize, SMEM_TOT);
    cudaFuncSetAttribute(mma_gemm<3>, cudaFuncAttributeMaxDynamicSharedMemorySize, SMEM_TOT);
    cudaFuncSetAttribute(mma_gemm<4>, cudaFuncAttributeMaxDynamicSharedMemorySize, SMEM_TOT);

    // 0) conversions (2 launches)
    conv_hl_kernel<<<(M_TOK * D_ + 255) / 256, 256>>>(src, src_h, src_l, M_TOK * D_);
    prep_all_kernel<<<(W_TOTAL + 255) / 256, 256>>>(vp_w, so_w, aw_w, op_w, l1_w, l2_w, w_h, w_l);

    const dim3 blk(256);
    const dim3 gfused(640 / 64, M_TOK / 128);  // (10, 64) = 640 CTAs
    const dim3 g256(256 / 64, M_TOK / 128);    // (4, 64)
    const dim3 g1024(1024 / 64, M_TOK / 128);  // (16, 64)

    // 1) fused: value | sampling_locations | attn logits
    mma_gemm<4><<<gfused, blk, SMEM_TOT>>>(src_h, src_l, w_h, w_l,
                                           vp_b, so_b, aw_b, nullptr, refpts,
                                           value, slocs, aw, nullptr, nullptr, 640, 256);
    // 2) gather (softmax fused) -> attn hi/lo
    gather_kernel<<<M_TOK, 256>>>(value, slocs, aw, attn_h, attn_l);
    // 3) out_proj + residual(src) -> tmpf
    mma_gemm<3><<<g256, blk, SMEM_TOT>>>(attn_h, attn_l, w_h + WOFF_OP, w_l + WOFF_OP,
                                         op_b, nullptr, nullptr, src, nullptr,
                                         tmpf, nullptr, nullptr, nullptr, nullptr, 256, 256);
    // 4) LN1 -> x1 (fp32 + hi/lo)
    layernorm_kernel<1><<<M_TOK / 8, 256>>>(tmpf, n1_g, n1_b, x1, x1_h, x1_l);
    // 5) FFN1: relu -> ffn hi/lo
    mma_gemm<2><<<g1024, blk, SMEM_TOT>>>(x1_h, x1_l, w_h + WOFF_L1, w_l + WOFF_L1,
                                          l1_b, nullptr, nullptr, nullptr, nullptr,
                                          nullptr, nullptr, nullptr, ffn_h, ffn_l, 1024, 256);
    // 6) FFN2 + residual(x1) -> tmpf
    mma_gemm<3><<<g256, blk, SMEM_TOT>>>(ffn_h, ffn_l, w_h + WOFF_L2, w_l + WOFF_L2,
                                         l2_b, nullptr, nullptr, x1, nullptr,
                                         tmpf, nullptr, nullptr, nullptr, nullptr, 256, 1024);
    // 7) LN2 -> final output
    layernorm_kernel<0><<<M_TOK / 8, 256>>>(tmpf, n2_g, n2_b, out_x, nullptr, nullptr);
}

// round 13
// speedup vs baseline: 2.9757x; 1.2652x over previous
#include <cuda_runtime.h>
#include <cuda_bf16.h>
#include <math.h>
#include <stdint.h>

// Problem constants (fixed by the reference setup)
#define BS   2
#define T_   4
#define HS   32
#define WS   32
#define HW   (HS*WS)          // 1024
#define LQ   (T_*HW)          // 4096
#define M_TOK (BS*LQ)         // 8192 rows
#define D_   256
#define NH   8
#define NL   4
#define NP   4
#define HD   32               // D/NH
#define DFFN 1024
#define X_ELEMS   (BS*LQ*D_)              // 2097152 (output x)

// ---------------- scratch (no allocations allowed) ----------------
__device__ __nv_bfloat16 g_src_h[M_TOK * D_];
// transposed weights [N][K], hi/lo; fused layout: vp | so | aw | op | l1 | l2
#define WOFF_VP 0
#define WOFF_SO 65536
#define WOFF_AW 131072
#define WOFF_OP 163840
#define WOFF_L1 229376
#define WOFF_L2 491520
#define W_TOTAL 753664
__device__ __nv_bfloat16 g_w_h[W_TOTAL];
__device__ __nv_bfloat16 g_w_l[W_TOTAL];

__device__ float g_value[M_TOK * D_];        // value fp32 for gather
__device__ float g_aw[M_TOK * 128];          // attention LOGITS (softmax fused in gather)
__device__ __nv_bfloat16 g_attn_h[M_TOK * D_];
__device__ float g_tmpf[M_TOK * D_];         // pre-LN buffer (reused)
__device__ float g_x1[M_TOK * D_];           // after LN1 (fp32 residual for FFN2)
__device__ __nv_bfloat16 g_x1_h[M_TOK * D_];
__device__ __nv_bfloat16 g_ffn_h[M_TOK * DFFN];

// ---------------- warp MMA helpers (baseline PTX, no 'a' features) --------
__device__ __forceinline__ uint32_t smem_u32(const void* p) {
    uint32_t a;
    asm("{ .reg .u64 t; cvta.to.shared.u64 t, %1; cvt.u32.u64 %0, t; }" : "=r"(a) : "l"(p));
    return a;
}
__device__ __forceinline__ void ldm_x4(uint32_t* r, uint32_t addr) {
    asm volatile("ldmatrix.sync.aligned.m8n8.x4.shared.b16 {%0,%1,%2,%3}, [%4];"
                 : "=r"(r[0]), "=r"(r[1]), "=r"(r[2]), "=r"(r[3]) : "r"(addr));
}
__device__ __forceinline__ void mma_bf16(float* c, const uint32_t* a, const uint32_t* b) {
    asm volatile("mma.sync.aligned.m16n8k16.row.col.f32.bf16.bf16.f32 "
                 "{%0,%1,%2,%3}, {%4,%5,%6,%7}, {%8,%9}, {%0,%1,%2,%3};"
                 : "+f"(c[0]), "+f"(c[1]), "+f"(c[2]), "+f"(c[3])
                 : "r"(a[0]), "r"(a[1]), "r"(a[2]), "r"(a[3]), "r"(b[0]), "r"(b[1]));
}
#define CP16(dst, src) \
    asm volatile("cp.async.cg.shared.global [%0], [%1], 16;" :: "r"(dst), "l"(src))
#define CP_COMMIT() asm volatile("cp.async.commit_group;" ::: "memory")
#define CP_WAIT1()  asm volatile("cp.async.wait_group 1;"  ::: "memory")

// ---------------- 2-pass bf16 GEMM: D = A·Wh + A·Wl (A plain bf16) ---------
// C[M,N] = A[M,K] @ W[K,N]; A bf16 [M][K], Wt hi/lo [N][K]
// EPI: 2 = relu -> bf16   3 = +bias+res (fp32)
//      4 = fused src-projections: region by n0: [0,256)=value fp32,
//          [256,512)=sampling-loc, [512,640)=attn logits
#define AST 40                    // smem row stride (bf16): 80B rows, 16B aligned
#define SSTR 20480                // bytes per pipeline stage (A 10240 + Bh 5120 + Bl 5120)
#define OFF_BH 10240
#define OFF_BL 15360
#define SMEM_TOT (2 * SSTR)       // 40960 B dynamic smem

template<int EPI>
__global__ __launch_bounds__(256)
void mma_gemm(const __nv_bfloat16* __restrict__ A,
              const __nv_bfloat16* __restrict__ Bhi, const __nv_bfloat16* __restrict__ Blo,
              const float* __restrict__ bias, const float* __restrict__ bias2,
              const float* __restrict__ bias3,
              const float* __restrict__ res, const float* __restrict__ ref,
              float* __restrict__ C, float* __restrict__ C2, float* __restrict__ C3,
              __nv_bfloat16* __restrict__ Chi,
              int N, int K)
{
    extern __shared__ char smem[];
    const uint32_t sb = smem_u32(smem);

    const int tid  = threadIdx.x;
    const int wid  = tid >> 5;
    const int lane = tid & 31;
    const int wm   = wid >> 1;          // 0..3  (M dir, 32 rows each)
    const int wn   = wid & 1;           // 0..1  (N dir, 32 cols each)
    const int m0   = blockIdx.y * 128;
    const int n0   = blockIdx.x * 64;

    const int seg = lane >> 3;
    const int rr  = lane & 7;

    uint32_t aoff[2], boff[2];
#pragma unroll
    for (int i = 0; i < 2; i++) {
        const int row = wm * 32 + i * 16 + (seg & 1) * 8 + rr;
        aoff[i] = (uint32_t)((row * AST + (seg >> 1) * 8) * 2);
    }
#pragma unroll
    for (int j = 0; j < 2; j++) {
        const int nrow = wn * 32 + j * 16 + ((seg >> 1) ? 8 : 0) + rr;
        boff[j] = (uint32_t)((nrow * AST + (seg & 1) * 8) * 2);
    }

    // per-thread load coords
    const int lrowA = tid >> 2;              // 0..63 (x2 halves for A)
    const int lc8   = (tid & 3) * 8;         // 0,8,16,24
    const uint32_t soA  = (uint32_t)((lrowA * AST + lc8) * 2);
    const uint32_t soA2 = (uint32_t)(((lrowA + 64) * AST + lc8) * 2);
    const uint32_t soB  = soA;

    float acc[2][4][4];
#pragma unroll
    for (int i = 0; i < 2; i++)
#pragma unroll
        for (int j = 0; j < 4; j++)
#pragma unroll
            for (int q = 0; q < 4; q++) acc[i][j][q] = 0.f;

    const int nch = K >> 5;     // K/32

    auto load_stage = [&](int kt, int s) {
        const int kc = kt << 5;
        const uint32_t st = sb + s * SSTR;
        size_t gi = (size_t)(m0 + lrowA) * K + kc + lc8;
        CP16(st + soA, A + gi);
        gi = (size_t)(m0 + 64 + lrowA) * K + kc + lc8;
        CP16(st + soA2, A + gi);
        gi = (size_t)(n0 + lrowA) * K + kc + lc8;
        CP16(st + OFF_BH + soB, Bhi + gi);
        CP16(st + OFF_BL + soB, Blo + gi);
    };

    load_stage(0, 0);
    CP_COMMIT();

    for (int kt = 0; kt < nch; kt++) {
        const int s = kt & 1;
        if (kt + 1 < nch) load_stage(kt + 1, s ^ 1);
        CP_COMMIT();
        CP_WAIT1();
        __syncthreads();

        const uint32_t st = sb + s * SSTR;
#pragma unroll
        for (int kk = 0; kk < 2; kk++) {
            const uint32_t kb = kk * 32;   // 16 bf16 = 32 bytes
            uint32_t ah[2][4], bh[2][4], bl[2][4];
#pragma unroll
            for (int i = 0; i < 2; i++) ldm_x4(ah[i], st + aoff[i] + kb);
#pragma unroll
            for (int j = 0; j < 2; j++) {
                ldm_x4(bh[j], st + OFF_BH + boff[j] + kb);
                ldm_x4(bl[j], st + OFF_BL + boff[j] + kb);
            }
#pragma unroll
            for (int i = 0; i < 2; i++) {
#pragma unroll
                for (int jt = 0; jt < 4; jt++) {
                    const int j = jt >> 1;
                    const int po = (jt & 1) * 2;
                    uint32_t bhp[2] = { bh[j][po], bh[j][po + 1] };
                    uint32_t blp[2] = { bl[j][po], bl[j][po + 1] };
                    mma_bf16(acc[i][jt], ah[i], bhp);
                    mma_bf16(acc[i][jt], ah[i], blp);
                }
            }
        }
        __syncthreads();
    }

    // -------- epilogue --------
    const int tg = lane >> 2;        // row-in-8
    const int t4 = lane & 3;         // col pair group

    int region = 0;
    const float* bptr = bias;
    float* optr = C;
    int oldN = N;
    int colbase = n0;
    if (EPI == 4) {
        if (n0 < 256)      { region = 0; bptr = bias;  optr = C;  oldN = 256; colbase = n0; }
        else if (n0 < 512) { region = 1; bptr = bias2; optr = C2; oldN = 256; colbase = n0 - 256; }
        else               { region = 2; bptr = bias3; optr = C3; oldN = 128; colbase = n0 - 512; }
    }

#pragma unroll
    for (int i = 0; i < 2; i++) {
#pragma unroll
        for (int jt = 0; jt < 4; jt++) {
            const int colg = colbase + wn * 32 + jt * 8 + t4 * 2;  // even col, 2 wide
            const float b0 = bptr[colg];
            const float b1 = bptr[colg + 1];
#pragma unroll
            for (int half = 0; half < 2; half++) {
                const int row = m0 + wm * 32 + i * 16 + tg + half * 8;
                float v0 = acc[i][jt][half * 2 + 0] + b0;
                float v1 = acc[i][jt][half * 2 + 1] + b1;
                if (EPI == 4 && region == 1) {
                    const int l = (colg >> 3) & 3;
                    const float r0 = ref[(size_t)row * 8 + l * 2 + 0];
                    const float r1 = ref[(size_t)row * 8 + l * 2 + 1];
                    v0 = v0 * (1.f / 32.f) + r0;
                    v1 = v1 * (1.f / 32.f) + r1;
                } else if (EPI == 3) {
                    const float2 rv = *(const float2*)(res + (size_t)row * N + colg);
                    v0 += rv.x; v1 += rv.y;
                }
                if (EPI == 2) {
                    v0 = fmaxf(v0, 0.f);
                    v1 = fmaxf(v1, 0.f);
                    __nv_bfloat162 hp;
                    hp.x = __float2bfloat16(v0);
                    hp.y = __float2bfloat16(v1);
                    *(__nv_bfloat162*)(Chi + (size_t)row * N + colg) = hp;
                } else {
                    float2 o; o.x = v0; o.y = v1;
                    *(float2*)(optr + (size_t)row * oldN + colg) = o;
                }
            }
        }
    }
}

// ---------------- fp32 -> bf16 elementwise ----------------
__global__ void conv_h_kernel(const float* __restrict__ x,
                              __nv_bfloat16* __restrict__ h, int n)
{
    const int i = blockIdx.x * blockDim.x + threadIdx.x;
    if (i >= n) return;
    h[i] = __float2bfloat16(x[i]);
}

// ---------------- all-weights transpose + split in one launch --------------
__global__ void prep_all_kernel(const float* __restrict__ vp, const float* __restrict__ so,
                                const float* __restrict__ awW, const float* __restrict__ op,
                                const float* __restrict__ l1, const float* __restrict__ l2,
                                __nv_bfloat16* __restrict__ h, __nv_bfloat16* __restrict__ l)
{
    const int i = blockIdx.x * blockDim.x + threadIdx.x;
    if (i >= W_TOTAL) return;
    const float* W;
    int K, N, base;
    if      (i < WOFF_SO) { W = vp;  K = 256;  N = 256;  base = WOFF_VP; }
    else if (i < WOFF_AW) { W = so;  K = 256;  N = 256;  base = WOFF_SO; }
    else if (i < WOFF_OP) { W = awW; K = 256;  N = 128;  base = WOFF_AW; }
    else if (i < WOFF_L1) { W = op;  K = 256;  N = 256;  base = WOFF_OP; }
    else if (i < WOFF_L2) { W = l1;  K = 256;  N = 1024; base = WOFF_L1; }
    else                  { W = l2;  K = 1024; N = 256;  base = WOFF_L2; }
    const int li = i - base;
    const int n = li / K;
    const int k = li - n * K;
    const float v = W[(size_t)k * N + n];
    const __nv_bfloat16 hv = __float2bfloat16(v);
    h[i] = hv;
    l[i] = __float2bfloat16(v - __bfloat162float(hv));
}

// ---------------- deformable gather: 3-phase, de-duplicated scalar work ----
// Block = one token m (8 warps = 8 heads).
// P0: 8 threads softmax the 16 logits of their head -> s_w
// P1: 128 threads compute 4 corner weights*w + PRE-SCALED indices (ci*D_)
// P2: each warp does 16 x (2 LDS.128 broadcast + 4 LDG + 4 FFMA), IADD-only addressing
__global__ __launch_bounds__(256)
void gather_kernel(const float* __restrict__ value, const float* __restrict__ slocs,
                   const float* __restrict__ logits,
                   __nv_bfloat16* __restrict__ outh)
{
    __shared__ float s_w[128];
    __shared__ float s_cw[128 * 4];
    __shared__ int   s_ci[128 * 4];

    const int m = blockIdx.x;
    const int tid = threadIdx.x;
    const int b = m >> 12;

    if (tid < 8) {
        const float* lg = logits + (size_t)m * 128 + tid * 16;
        float w[16];
        float mx = -1e30f;
#pragma unroll
        for (int i = 0; i < 16; i++) { w[i] = lg[i]; mx = fmaxf(mx, w[i]); }
        float ssum = 0.f;
#pragma unroll
        for (int i = 0; i < 16; i++) { w[i] = __expf(w[i] - mx); ssum += w[i]; }
        const float sinv = 1.f / ssum;
#pragma unroll
        for (int i = 0; i < 16; i++) s_w[tid * 16 + i] = w[i] * sinv;
    }
    __syncthreads();

    if (tid < 128) {
        const int h = tid >> 4;
        const int s = tid & 15;
        const int l = s >> 2;
        const float* sl = slocs + (((size_t)m * NH + h) * 16 + s) * 2;
        const float x = sl[0] * (float)WS - 0.5f;
        const float y = sl[1] * (float)HS - 0.5f;
        const float ww = s_w[tid];
        const float x0f = floorf(x);
        const float y0f = floorf(y);
        const int x0 = (int)x0f;
        const int y0 = (int)y0f;
        const float lx = x - x0f;
        const float ly = y - y0f;
        const int vbase = b * LQ + l * HW;
#pragma unroll
        for (int dy = 0; dy < 2; dy++) {
            const int yi = y0 + dy;
            const float wy = dy ? ly : (1.f - ly);
#pragma unroll
            for (int dx = 0; dx < 2; dx++) {
                const int xi = x0 + dx;
                const float wx = dx ? lx : (1.f - lx);
                const bool valid = (yi >= 0) & (yi < HS) & (xi >= 0) & (xi < WS);
                const int yc = min(max(yi, 0), HS - 1);
                const int xc = min(max(xi, 0), WS - 1);
                const int ci = tid * 4 + dy * 2 + dx;
                s_cw[ci] = valid ? (ww * wy * wx) : 0.f;
                s_ci[ci] = (vbase + yc * WS + xc) * D_;   // pre-scaled by row stride
            }
        }
    }
    __syncthreads();

    const int h = tid >> 5;
    const int d = tid & 31;
    const int hb = h * HD + d;
    float acc = 0.f;
#pragma unroll
    for (int s = 0; s < 16; s++) {
        const int si = (h * 16 + s) * 4;
        const float4 cw = *(const float4*)&s_cw[si];
        const int4   ci = *(const int4*)&s_ci[si];
        acc = fmaf(cw.x, value[ci.x + hb], acc);
        acc = fmaf(cw.y, value[ci.y + hb], acc);
        acc = fmaf(cw.z, value[ci.z + hb], acc);
        acc = fmaf(cw.w, value[ci.w + hb], acc);
    }
    outh[(size_t)m * D_ + hb] = __float2bfloat16(acc);
}

// ---------------- layernorm over 256 cols; one warp per row ----------------
// MODE 0: fp32 out only. MODE 1: fp32 out + bf16 out.
template<int MODE>
__global__ __launch_bounds__(256)
void layernorm_kernel(const float* __restrict__ in, const float* __restrict__ g,
                      const float* __restrict__ b, float* __restrict__ out,
                      __nv_bfloat16* __restrict__ outh)
{
    const int row = blockIdx.x * 8 + (threadIdx.x >> 5);
    const int lane = threadIdx.x & 31;
    const float* r = in + (size_t)row * D_;
    float v[8];
    float s = 0.f, s2 = 0.f;
#pragma unroll
    for (int i = 0; i < 8; i++) {
        v[i] = r[i * 32 + lane];
        s += v[i];
        s2 = fmaf(v[i], v[i], s2);
    }
#pragma unroll
    for (int o = 16; o > 0; o >>= 1) {
        s  += __shfl_xor_sync(0xffffffff, s, o);
        s2 += __shfl_xor_sync(0xffffffff, s2, o);
    }
    const float mean = s * (1.f / 256.f);
    const float var  = s2 * (1.f / 256.f) - mean * mean;
    const float inv  = rsqrtf(var + 1e-5f);
#pragma unroll
    for (int i = 0; i < 8; i++) {
        const int c = i * 32 + lane;
        const float u = (v[i] - mean) * inv * g[c] + b[c];
        out[(size_t)row * D_ + c] = u;
        if (MODE == 1) outh[(size_t)row * D_ + c] = __float2bfloat16(u);
    }
}

// ---------------- host launch ----------------
extern "C" void kernel_launch(void* const* d_in, const int* in_sizes, int n_in,
                              void* d_out, int out_size)
{
    const float* src    = (const float*)d_in[0];
    // d_in[1] = pos (unused by the reference forward)
    const float* refpts = (const float*)d_in[2];
    const float* vp_w   = (const float*)d_in[3];
    const float* vp_b   = (const float*)d_in[4];
    const float* so_w   = (const float*)d_in[5];
    const float* so_b   = (const float*)d_in[6];
    const float* aw_w   = (const float*)d_in[7];
    const float* aw_b   = (const float*)d_in[8];
    const float* op_w   = (const float*)d_in[9];
    const float* op_b   = (const float*)d_in[10];
    const float* n1_g   = (const float*)d_in[11];
    const float* n1_b   = (const float*)d_in[12];
    const float* l1_w   = (const float*)d_in[13];
    const float* l1_b   = (const float*)d_in[14];
    const float* l2_w   = (const float*)d_in[15];
    const float* l2_b   = (const float*)d_in[16];
    const float* n2_g   = (const float*)d_in[17];
    const float* n2_b   = (const float*)d_in[18];

    float* out_x = (float*)d_out;
    float* slocs = (float*)d_out + X_ELEMS;

    __nv_bfloat16 *src_h, *w_h, *w_l, *attn_h, *x1_h, *ffn_h;
    float *value, *aw, *tmpf, *x1;
    cudaGetSymbolAddress((void**)&src_h, g_src_h);
    cudaGetSymbolAddress((void**)&w_h,   g_w_h);
    cudaGetSymbolAddress((void**)&w_l,   g_w_l);
    cudaGetSymbolAddress((void**)&value, g_value);
    cudaGetSymbolAddress((void**)&aw,    g_aw);
    cudaGetSymbolAddress((void**)&attn_h, g_attn_h);
    cudaGetSymbolAddress((void**)&tmpf,  g_tmpf);
    cudaGetSymbolAddress((void**)&x1,    g_x1);
    cudaGetSymbolAddress((void**)&x1_h,  g_x1_h);
    cudaGetSymbolAddress((void**)&ffn_h, g_ffn_h);

    cudaFuncSetAttribute(mma_gemm<2>, cudaFuncAttributeMaxDynamicSharedMemorySize, SMEM_TOT);
    cudaFuncSetAttribute(mma_gemm<3>, cudaFuncAttributeMaxDynamicSharedMemorySize, SMEM_TOT);
    cudaFuncSetAttribute(mma_gemm<4>, cudaFuncAttributeMaxDynamicSharedMemorySize, SMEM_TOT);

    // 0) conversions (2 launches)
    conv_h_kernel<<<(M_TOK * D_ + 255) / 256, 256>>>(src, src_h, M_TOK * D_);
    prep_all_kernel<<<(W_TOTAL + 255) / 256, 256>>>(vp_w, so_w, aw_w, op_w, l1_w, l2_w, w_h, w_l);

    const dim3 blk(256);
    const dim3 gfused(640 / 64, M_TOK / 128);  // (10, 64) = 640 CTAs
    const dim3 g256(256 / 64, M_TOK / 128);    // (4, 64)
    const dim3 g1024(1024 / 64, M_TOK / 128);  // (16, 64)

    // 1) fused: value | sampling_locations | attn logits
    mma_gemm<4><<<gfused, blk, SMEM_TOT>>>(src_h, w_h, w_l,
                                           vp_b, so_b, aw_b, nullptr, refpts,
                                           value, slocs, aw, nullptr, 640, 256);
    // 2) gather (softmax fused) -> attn bf16
    gather_kernel<<<M_TOK, 256>>>(value, slocs, aw, attn_h);
    // 3) out_proj + residual(src) -> tmpf
    mma_gemm<3><<<g256, blk, SMEM_TOT>>>(attn_h, w_h + WOFF_OP, w_l + WOFF_OP,
                                         op_b, nullptr, nullptr, src, nullptr,
                                         tmpf, nullptr, nullptr, nullptr, 256, 256);
    // 4) LN1 -> x1 (fp32 + bf16)
    layernorm_kernel<1><<<M_TOK / 8, 256>>>(tmpf, n1_g, n1_b, x1, x1_h);
    // 5) FFN1: relu -> ffn bf16
    mma_gemm<2><<<g1024, blk, SMEM_TOT>>>(x1_h, w_h + WOFF_L1, w_l + WOFF_L1,
                                          l1_b, nullptr, nullptr, nullptr, nullptr,
                                          nullptr, nullptr, nullptr, ffn_h, 1024, 256);
    // 6) FFN2 + residual(x1) -> tmpf
    mma_gemm<3><<<g256, blk, SMEM_TOT>>>(ffn_h, w_h + WOFF_L2, w_l + WOFF_L2,
                                         l2_b, nullptr, nullptr, x1, nullptr,
                                         tmpf, nullptr, nullptr, nullptr, 256, 1024);
    // 7) LN2 -> final output
    layernorm_kernel<0><<<M_TOK / 8, 256>>>(tmpf, n2_g, n2_b, out_x, nullptr);
}